// round 1
// baseline (speedup 1.0000x reference)
#include <cuda_runtime.h>
#include <cuda_bf16.h>
#include <math.h>

// ---------------- problem constants ----------------
#define Bv      8
#define Lv      32
#define BLv     256          // B*L
#define DIMv    2048
#define KV_RANKv 512
#define Q_RANKv 768
#define Hv      16
#define D_NRv   128
#define D_Rv    64
#define D_Vv    128
#define QKv     192          // D_NR + D_R
#define MAXTv   4096
#define STARTv  4064
#define KCATv   576          // KV_RANK + D_R
#define EPSv    1.1920929e-07f
#define SCALEv  0.07216878364870323f   // 1/sqrt(192)

// ---------------- scratch (device globals; allocation-free) ----------------
__device__ float g_qlin  [BLv * Q_RANKv];
__device__ float g_qdn   [BLv * Q_RANKv];
__device__ float g_q     [BLv * Hv * QKv];       // 256 x 3072
__device__ float g_kv    [BLv * KCATv];          // 256 x 576
__device__ float g_Acat  [Bv * 512 * KCATv];     // rows = b*512 + h*32 + l
__device__ float g_Kcat  [Bv * MAXTv * KCATv];   // 75.5 MB
__device__ float g_scores[(long long)Bv * 512 * MAXTv]; // 67 MB, becomes P
__device__ float g_O     [Bv * 512 * 512];
__device__ float g_o2    [BLv * Hv * D_Vv];      // 256 x 2048

// ---------------- generic tiled SGEMM ----------------
// BT=true : C[M,N] = A[M,K] * B[N,K]^T    (B row-major N x K)
// BT=false: C[M,N] = A[M,K] * B[K,N]      (B row-major K x N)
// M,N multiples of 64; K multiple of 16; all lds multiples of 4.
#define GBM 64
#define GBN 64
#define GBK 16

template <bool BT>
__global__ void gemm_kernel(const float* __restrict__ A,
                            const float* __restrict__ Bm,
                            float* __restrict__ C,
                            int M, int N, int K,
                            int lda, int ldb, int ldc,
                            long long sA, long long sB, long long sC)
{
    __shared__ float As[GBK][GBM + 4];
    __shared__ float Bs[GBK][GBN + 4];

    const int bz = blockIdx.z;
    A  += bz * sA;
    Bm += bz * sB;
    C  += bz * sC;

    const int m0 = blockIdx.y * GBM;
    const int n0 = blockIdx.x * GBN;
    const int tid = threadIdx.x;         // 256 threads
    const int tx = tid & 15;
    const int ty = tid >> 4;

    float acc[4][4] = {};

    for (int k0 = 0; k0 < K; k0 += GBK) {
        // ---- stage A tile (64x16), transposed into As[k][m]
        {
            const int r  = tid >> 2;
            const int kq = (tid & 3) * 4;
            const float4 a = *(const float4*)(A + (long long)(m0 + r) * lda + k0 + kq);
            As[kq + 0][r] = a.x;
            As[kq + 1][r] = a.y;
            As[kq + 2][r] = a.z;
            As[kq + 3][r] = a.w;
        }
        // ---- stage B tile
        if (BT) {
            const int r  = tid >> 2;
            const int kq = (tid & 3) * 4;
            const float4 b = *(const float4*)(Bm + (long long)(n0 + r) * ldb + k0 + kq);
            Bs[kq + 0][r] = b.x;
            Bs[kq + 1][r] = b.y;
            Bs[kq + 2][r] = b.z;
            Bs[kq + 3][r] = b.w;
        } else {
            const int kk = tid >> 4;           // 0..15
            const int cq = (tid & 15) * 4;     // 0..60
            const float4 b = *(const float4*)(Bm + (long long)(k0 + kk) * ldb + n0 + cq);
            *(float4*)&Bs[kk][cq] = b;
        }
        __syncthreads();

        #pragma unroll
        for (int k = 0; k < GBK; k++) {
            const float4 a4 = *(const float4*)&As[k][ty * 4];
            const float4 b4 = *(const float4*)&Bs[k][tx * 4];
            const float ar[4] = {a4.x, a4.y, a4.z, a4.w};
            const float br[4] = {b4.x, b4.y, b4.z, b4.w};
            #pragma unroll
            for (int i = 0; i < 4; i++)
                #pragma unroll
                for (int j = 0; j < 4; j++)
                    acc[i][j] += ar[i] * br[j];
        }
        __syncthreads();
    }

    #pragma unroll
    for (int i = 0; i < 4; i++) {
        const int m = m0 + ty * 4 + i;
        float4 o;
        o.x = acc[i][0]; o.y = acc[i][1]; o.z = acc[i][2]; o.w = acc[i][3];
        *(float4*)(C + (long long)m * ldc + n0 + tx * 4) = o;
    }
}

// ---------------- rmsnorm over Q_RANK=768 per row ----------------
__global__ void rmsnorm_kernel(const float* __restrict__ xin,
                               const float* __restrict__ w,
                               float* __restrict__ yout)
{
    const int r = blockIdx.x;
    const int tid = threadIdx.x;   // 256
    const float* xr = xin + r * Q_RANKv;
    float s = 0.f;
    #pragma unroll
    for (int i = 0; i < 3; i++) {
        const float v = xr[tid + i * 256];
        s += v * v;
    }
    __shared__ float red[256];
    red[tid] = s;
    __syncthreads();
    for (int o = 128; o > 0; o >>= 1) {
        if (tid < o) red[tid] += red[tid + o];
        __syncthreads();
    }
    const float inv = rsqrtf(red[0] / (float)Q_RANKv + EPSv);
    #pragma unroll
    for (int i = 0; i < 3; i++) {
        const int c = tid + i * 256;
        yout[r * Q_RANKv + c] = xr[c] * inv * w[c];
    }
}

// ---------------- rope (in-place on g_q rope slice and g_kv rope slice) ----
__global__ void rope_kernel(float* __restrict__ q, float* __restrict__ kv,
                            const float* __restrict__ fc,
                            const float* __restrict__ fs)
{
    const int bl = blockIdx.x;
    const int l = bl & 31;
    const int tid = threadIdx.x;  // 256 >= 512? -> use 2 lanes per thread
    // 512 q pairs + 32 kv pairs = 544 work items; 256 threads, strided
    for (int wk = tid; wk < 544; wk += 256) {
        if (wk < 512) {
            const int h = wk >> 5;
            const int j = wk & 31;
            const float c = fc[l * 32 + j];
            const float s = fs[l * 32 + j];
            float* p = q + bl * (Hv * QKv) + h * QKv + D_NRv + 2 * j;
            const float xr = p[0], xi = p[1];
            p[0] = xr * c - xi * s;
            p[1] = xr * s + xi * c;
        } else {
            const int j = wk - 512;
            const float c = fc[l * 32 + j];
            const float s = fs[l * 32 + j];
            float* p = kv + bl * KCATv + KV_RANKv + 2 * j;
            const float xr = p[0], xi = p[1];
            p[0] = xr * c - xi * s;
            p[1] = xr * s + xi * c;
        }
    }
}

// ---------------- build Acat: q absorbed through W_kv_up (nrope) + q_rope ---
__global__ void build_acat_kernel(const float* __restrict__ q,
                                  const float* __restrict__ w_kv_up,
                                  float* __restrict__ Acat)
{
    const int bl = blockIdx.x;       // 0..255
    const int h  = blockIdx.y;       // 0..15
    const int b = bl >> 5, l = bl & 31;
    const int row = b * 512 + h * 32 + l;
    const int tid = threadIdx.x;     // 256

    __shared__ float qs[D_NRv];
    if (tid < D_NRv) qs[tid] = q[bl * (Hv * QKv) + h * QKv + tid];
    __syncthreads();

    const float* w = w_kv_up + (long long)(h * 256) * KV_RANKv;
    float a0 = 0.f, a1 = 0.f;
    #pragma unroll 4
    for (int d = 0; d < D_NRv; d++) {
        const float qd = qs[d];
        a0 += qd * w[d * KV_RANKv + tid];
        a1 += qd * w[d * KV_RANKv + tid + 256];
    }
    float* drow = Acat + (long long)row * KCATv;
    drow[tid]       = a0;
    drow[tid + 256] = a1;
    if (tid < D_Rv)
        drow[KV_RANKv + tid] = q[bl * (Hv * QKv) + h * QKv + D_NRv + tid];
}

// ---------------- build Kcat: [kv_latent | k_rope], cache or fresh ----------
__global__ void build_kcat_kernel(const float* __restrict__ kvc,
                                  const float* __restrict__ krc,
                                  const float* __restrict__ kvfresh,
                                  float* __restrict__ Kcat)
{
    const int t = blockIdx.x;   // 0..4095
    const int b = blockIdx.y;   // 0..7
    const int tid = threadIdx.x; // 256
    float* dst = Kcat + ((long long)b * MAXTv + t) * KCATv;
    if (t < STARTv) {
        const float* skv = kvc + ((long long)b * MAXTv + t) * KV_RANKv;
        const float* skr = krc + ((long long)b * MAXTv + t) * D_Rv;
        for (int c = tid; c < KCATv; c += 256)
            dst[c] = (c < KV_RANKv) ? skv[c] : skr[c - KV_RANKv];
    } else {
        const float* src = kvfresh + (b * Lv + (t - STARTv)) * KCATv;
        for (int c = tid; c < KCATv; c += 256)
            dst[c] = src[c];
    }
}

// ---------------- softmax with scale + mask, in place ----------------------
__global__ void softmax_kernel(float* __restrict__ scores,
                               const float* __restrict__ mask)
{
    const int id = blockIdx.x;           // b*512 + h*32 + l
    const int l = id & 31;
    const int tid = threadIdx.x;         // 256
    float* row = scores + (long long)id * MAXTv;
    const float* mrow = mask + l * MAXTv;

    float vals[16];
    float vmax = -3.4e38f;
    #pragma unroll
    for (int i = 0; i < 16; i++) {
        const int t = tid + i * 256;
        const float v = row[t] * SCALEv + mrow[t];
        vals[i] = v;
        vmax = fmaxf(vmax, v);
    }
    __shared__ float red[256];
    red[tid] = vmax;
    __syncthreads();
    for (int o = 128; o > 0; o >>= 1) {
        if (tid < o) red[tid] = fmaxf(red[tid], red[tid + o]);
        __syncthreads();
    }
    const float m = red[0];
    __syncthreads();

    float sum = 0.f;
    #pragma unroll
    for (int i = 0; i < 16; i++) {
        const float e = expf(vals[i] - m);
        vals[i] = e;
        sum += e;
    }
    red[tid] = sum;
    __syncthreads();
    for (int o = 128; o > 0; o >>= 1) {
        if (tid < o) red[tid] += red[tid + o];
        __syncthreads();
    }
    const float inv = 1.0f / red[0];
    #pragma unroll
    for (int i = 0; i < 16; i++)
        row[tid + i * 256] = vals[i] * inv;
}

// ---------------- o through V-up part of W_kv_up ---------------------------
__global__ void o_up_kernel(const float* __restrict__ O,
                            const float* __restrict__ w_kv_up,
                            float* __restrict__ o2)
{
    const int bl = blockIdx.x;   // 0..255
    const int h  = blockIdx.y;   // 0..15
    const int b = bl >> 5, l = bl & 31;
    const int tid = threadIdx.x; // 128, one per output d

    __shared__ float os[KV_RANKv];
    const float* orow = O + (long long)(b * 512 + h * 32 + l) * KV_RANKv;
    for (int c = tid; c < KV_RANKv; c += 128)
        os[c] = orow[c];
    __syncthreads();

    const float* w = w_kv_up + (long long)(h * 256 + 128 + tid) * KV_RANKv;
    float acc = 0.f;
    #pragma unroll 4
    for (int k = 0; k < KV_RANKv; k += 4) {
        const float4 w4 = *(const float4*)(w + k);
        acc += os[k] * w4.x + os[k + 1] * w4.y + os[k + 2] * w4.z + os[k + 3] * w4.w;
    }
    o2[bl * (Hv * D_Vv) + h * D_Vv + tid] = acc;
}

// ---------------- launch --------------------------------------------------
extern "C" void kernel_launch(void* const* d_in, const int* in_sizes, int n_in,
                              void* d_out, int out_size)
{
    const float* x         = (const float*)d_in[0];
    // d_in[1] = start_pos (constant 4064, baked in)
    const float* freq_cos  = (const float*)d_in[2];
    const float* freq_sin  = (const float*)d_in[3];
    const float* mask      = (const float*)d_in[4];
    const float* kvc       = (const float*)d_in[5];
    const float* krc       = (const float*)d_in[6];
    const float* w_kv_down = (const float*)d_in[7];
    const float* w_q_down  = (const float*)d_in[8];
    const float* rms_q_w   = (const float*)d_in[9];
    const float* w_q_up    = (const float*)d_in[10];
    const float* w_kv_up   = (const float*)d_in[11];
    const float* w_out     = (const float*)d_in[12];
    float* out = (float*)d_out;

    float *qlin, *qdn, *q, *kv, *Acat, *Kcat, *scores, *O, *o2;
    cudaGetSymbolAddress((void**)&qlin,   g_qlin);
    cudaGetSymbolAddress((void**)&qdn,    g_qdn);
    cudaGetSymbolAddress((void**)&q,      g_q);
    cudaGetSymbolAddress((void**)&kv,     g_kv);
    cudaGetSymbolAddress((void**)&Acat,   g_Acat);
    cudaGetSymbolAddress((void**)&Kcat,   g_Kcat);
    cudaGetSymbolAddress((void**)&scores, g_scores);
    cudaGetSymbolAddress((void**)&O,      g_O);
    cudaGetSymbolAddress((void**)&o2,     g_o2);

    // 1) q_down: (256,2048) x (768,2048)^T
    gemm_kernel<true><<<dim3(Q_RANKv / GBN, BLv / GBM, 1), 256>>>(
        x, w_q_down, qlin, BLv, Q_RANKv, DIMv, DIMv, DIMv, Q_RANKv, 0, 0, 0);

    // 2) kv_down: (256,2048) x (576,2048)^T
    gemm_kernel<true><<<dim3(KCATv / GBN, BLv / GBM, 1), 256>>>(
        x, w_kv_down, kv, BLv, KCATv, DIMv, DIMv, DIMv, KCATv, 0, 0, 0);

    // 3) rmsnorm
    rmsnorm_kernel<<<BLv, 256>>>(qlin, rms_q_w, qdn);

    // 4) q_up: (256,768) x (3072,768)^T
    gemm_kernel<true><<<dim3((Hv * QKv) / GBN, BLv / GBM, 1), 256>>>(
        qdn, w_q_up, q, BLv, Hv * QKv, Q_RANKv, Q_RANKv, Q_RANKv, Hv * QKv, 0, 0, 0);

    // 5) rope on q_rope and fresh k_rope
    rope_kernel<<<BLv, 256>>>(q, kv, freq_cos, freq_sin);

    // 6) Acat = [q_nrope @ W_up_nr | q_rope]   rows (b,h,l)
    build_acat_kernel<<<dim3(BLv, Hv), 256>>>(q, w_kv_up, Acat);

    // 7) Kcat = [kv_latent | k_rope] (cache rows + fresh rows)
    build_kcat_kernel<<<dim3(MAXTv, Bv), 256>>>(kvc, krc, kv, Kcat);

    // 8) scores = Acat @ Kcat^T, batched over b: (512,4096,576)
    gemm_kernel<true><<<dim3(MAXTv / GBN, 512 / GBM, Bv), 256>>>(
        Acat, Kcat, scores, 512, MAXTv, KCATv, KCATv, KCATv, MAXTv,
        (long long)512 * KCATv, (long long)MAXTv * KCATv, (long long)512 * MAXTv);

    // 9) softmax (scale + mask fused)
    softmax_kernel<<<Bv * 512, 256>>>(scores, mask);

    // 10) O = P @ kvc, batched: (512,512,4096); B = Kcat first 512 cols (ldb 576)
    gemm_kernel<false><<<dim3(512 / GBN, 512 / GBM, Bv), 256>>>(
        scores, Kcat, O, 512, KV_RANKv, MAXTv, MAXTv, KCATv, KV_RANKv,
        (long long)512 * MAXTv, (long long)MAXTv * KCATv, (long long)512 * KV_RANKv);

    // 11) o2 = O @ W_up_v^T per head
    o_up_kernel<<<dim3(BLv, Hv), 128>>>(O, w_kv_up, o2);

    // 12) out = o2 @ w_out^T : (256,2048) x (2048,2048)^T
    gemm_kernel<true><<<dim3(DIMv / GBN, BLv / GBM, 1), 256>>>(
        o2, w_out, out, BLv, DIMv, DIMv, DIMv, DIMv, DIMv, 0, 0, 0);
}

// round 3
// speedup vs baseline: 1.3663x; 1.3663x over previous
#include <cuda_runtime.h>
#include <math.h>
#include <stdint.h>

// ---------------- problem constants ----------------
#define Bv      8
#define Lv      32
#define BLv     256          // B*L
#define DIMv    2048
#define KV_RANKv 512
#define Q_RANKv 768
#define Hv      16
#define D_NRv   128
#define D_Rv    64
#define D_Vv    128
#define QKv     192          // D_NR + D_R
#define MAXTv   4096
#define STARTv  4064
#define KCATv   576          // KV_RANK + D_R
#define EPSv    1.1920929e-07f
#define SCALEv  0.07216878364870323f   // 1/sqrt(192)

// ---------------- scratch (device globals; allocation-free) ----------------
__device__ float g_qlin  [BLv * Q_RANKv];
__device__ float g_qdn   [BLv * Q_RANKv];
__device__ float g_q     [BLv * Hv * QKv];
__device__ float g_kv    [BLv * KCATv];
__device__ float g_Acat  [Bv * 512 * KCATv];
__device__ float g_Kcat  [Bv * MAXTv * KCATv];
__device__ float g_scores[(long long)Bv * 512 * MAXTv];
__device__ float g_O     [Bv * 512 * 512];
__device__ float g_o2    [BLv * Hv * D_Vv];

// ---------------- bf16 bit helpers (no bf16 types) ----------------
__device__ __forceinline__ unsigned short bf16_rn(float x) {
    unsigned int u = __float_as_uint(x);
    unsigned int r = u + 0x7FFFu + ((u >> 16) & 1u);
    return (unsigned short)(r >> 16);
}
__device__ __forceinline__ float bf16_tof(unsigned short h) {
    return __uint_as_float(((unsigned int)h) << 16);
}
// split pair (x,y) into packed hi and lo bf16x2 words
__device__ __forceinline__ void split2(float x, float y,
                                       unsigned int* hi, unsigned int* lo) {
    unsigned short hx = bf16_rn(x);
    unsigned short hy = bf16_rn(y);
    unsigned short lx = bf16_rn(x - bf16_tof(hx));
    unsigned short ly = bf16_rn(y - bf16_tof(hy));
    *hi = (unsigned int)hx | ((unsigned int)hy << 16);
    *lo = (unsigned int)lx | ((unsigned int)ly << 16);
}

__device__ __forceinline__ void ldmx4(unsigned int* r, const unsigned int* p) {
    unsigned int a = (unsigned int)__cvta_generic_to_shared(p);
    asm volatile("ldmatrix.sync.aligned.m8n8.x4.shared.b16 {%0,%1,%2,%3}, [%4];"
                 : "=r"(r[0]), "=r"(r[1]), "=r"(r[2]), "=r"(r[3]) : "r"(a));
}

__device__ __forceinline__ void mma16816(float* c, const unsigned int* a,
                                         unsigned int b0, unsigned int b1) {
    asm volatile(
        "mma.sync.aligned.m16n8k16.row.col.f32.bf16.bf16.f32 "
        "{%0,%1,%2,%3},{%4,%5,%6,%7},{%8,%9},{%0,%1,%2,%3};\n"
        : "+f"(c[0]), "+f"(c[1]), "+f"(c[2]), "+f"(c[3])
        : "r"(a[0]), "r"(a[1]), "r"(a[2]), "r"(a[3]), "r"(b0), "r"(b1));
}

// ====================================================================
//  split-bf16 tensor-core GEMM: C[M,N] = A[M,K] * op(B), fp32 in/out.
//  BT=true : B is [N,K] row-major.  BT=false: B is [K,N] row-major.
//  M%128==0, N%128==0, K%32==0, all pointers 16B aligned per row.
//  smem rows are 20 uint32 = 40 bf16 (32 data + 8 pad) => 80B stride.
// ====================================================================
#define SROW 20

template <bool BT>
__global__ __launch_bounds__(256)
void gemm_tc(const float* __restrict__ A, const float* __restrict__ Bm,
             float* __restrict__ C,
             int M, int N, int K, int lda, int ldb, int ldc,
             long long sA, long long sB, long long sC)
{
    __shared__ __align__(16) unsigned int Ah[128][SROW];
    __shared__ __align__(16) unsigned int Al[128][SROW];
    __shared__ __align__(16) unsigned int Bh[128][SROW];
    __shared__ __align__(16) unsigned int Bl[128][SROW];

    const int bz = blockIdx.z;
    A  += bz * sA;
    Bm += bz * sB;
    C  += bz * sC;

    const int m0 = blockIdx.y * 128;
    const int n0 = blockIdx.x * 128;
    const int tid  = threadIdx.x;
    const int wid  = tid >> 5;
    const int lane = tid & 31;
    const int wm = (wid & 1) * 64;
    const int wn = (wid >> 1) * 32;
    const int lr = lane & 7;
    const int lg = lane >> 3;

    float c[4][4][4];
    #pragma unroll
    for (int i = 0; i < 4; i++)
        #pragma unroll
        for (int j = 0; j < 4; j++)
            #pragma unroll
            for (int t = 0; t < 4; t++)
                c[i][j][t] = 0.0f;

    const int srow = tid >> 1;        // 0..127
    const int skb  = (tid & 1) * 16;  // bf16 col base: 0 or 16

    for (int k0 = 0; k0 < K; k0 += 32) {
        // ---- stage A tile (128 x 32) with hi/lo split, packed words
        #pragma unroll
        for (int i = 0; i < 4; i++) {
            const int k = skb + 4 * i;
            const float4 v = *(const float4*)(A + (long long)(m0 + srow) * lda + k0 + k);
            unsigned int h0, l0, h1, l1;
            split2(v.x, v.y, &h0, &l0);
            split2(v.z, v.w, &h1, &l1);
            Ah[srow][(k >> 1) + 0] = h0;
            Ah[srow][(k >> 1) + 1] = h1;
            Al[srow][(k >> 1) + 0] = l0;
            Al[srow][(k >> 1) + 1] = l1;
        }
        // ---- stage B tile into [n][k] layout
        if (BT) {
            #pragma unroll
            for (int i = 0; i < 4; i++) {
                const int k = skb + 4 * i;
                const float4 v = *(const float4*)(Bm + (long long)(n0 + srow) * ldb + k0 + k);
                unsigned int h0, l0, h1, l1;
                split2(v.x, v.y, &h0, &l0);
                split2(v.z, v.w, &h1, &l1);
                Bh[srow][(k >> 1) + 0] = h0;
                Bh[srow][(k >> 1) + 1] = h1;
                Bl[srow][(k >> 1) + 0] = l0;
                Bl[srow][(k >> 1) + 1] = l1;
            }
        } else {
            const int kk2 = tid >> 3;   // k row 0..31
            const int nqb = tid & 7;
            #pragma unroll
            for (int i = 0; i < 4; i++) {
                const int n = 4 * (nqb + 8 * i);
                const float4 v = *(const float4*)(Bm + (long long)(k0 + kk2) * ldb + n0 + n);
                const float vv[4] = {v.x, v.y, v.z, v.w};
                #pragma unroll
                for (int j = 0; j < 4; j++) {
                    const unsigned short h = bf16_rn(vv[j]);
                    const unsigned short l = bf16_rn(vv[j] - bf16_tof(h));
                    ((unsigned short*)&Bh[n + j][0])[kk2] = h;
                    ((unsigned short*)&Bl[n + j][0])[kk2] = l;
                }
            }
        }
        __syncthreads();

        #pragma unroll
        for (int kk = 0; kk < 32; kk += 16) {
            unsigned int ah[4][4], al[4][4];
            #pragma unroll
            for (int im = 0; im < 4; im++) {
                const int mrow = wm + im * 16 + lr + ((lg & 1) << 3);
                const int kw   = (kk + ((lg & 2) << 2)) >> 1;
                ldmx4(ah[im], &Ah[mrow][kw]);
                ldmx4(al[im], &Al[mrow][kw]);
            }
            unsigned int bh[2][4], bl[2][4];
            #pragma unroll
            for (int j2 = 0; j2 < 2; j2++) {
                const int nrow = wn + j2 * 16 + lr + ((lg & 2) << 2);
                const int kw   = (kk + ((lg & 1) << 3)) >> 1;
                ldmx4(bh[j2], &Bh[nrow][kw]);
                ldmx4(bl[j2], &Bl[nrow][kw]);
            }
            #pragma unroll
            for (int im = 0; im < 4; im++) {
                #pragma unroll
                for (int j2 = 0; j2 < 2; j2++) {
                    #pragma unroll
                    for (int t = 0; t < 2; t++) {
                        const int jn = j2 * 2 + t;
                        mma16816(c[im][jn], ah[im], bh[j2][t * 2], bh[j2][t * 2 + 1]);
                        mma16816(c[im][jn], ah[im], bl[j2][t * 2], bl[j2][t * 2 + 1]);
                        mma16816(c[im][jn], al[im], bh[j2][t * 2], bh[j2][t * 2 + 1]);
                    }
                }
            }
        }
        __syncthreads();
    }

    #pragma unroll
    for (int im = 0; im < 4; im++) {
        const int row = m0 + wm + im * 16 + (lane >> 2);
        #pragma unroll
        for (int jn = 0; jn < 4; jn++) {
            const int col = n0 + wn + jn * 8 + (lane & 3) * 2;
            float2 v0, v1;
            v0.x = c[im][jn][0];
            v0.y = c[im][jn][1];
            v1.x = c[im][jn][2];
            v1.y = c[im][jn][3];
            *(float2*)(C + (long long)row * ldc + col)       = v0;
            *(float2*)(C + (long long)(row + 8) * ldc + col) = v1;
        }
    }
}

// ---------------- fp32 tiled SGEMM (kv_down: N=576 not /128) ----------------
#define GBM 64
#define GBN 64
#define GBK 16

__global__ void gemm_kernel_bt(const float* __restrict__ A,
                               const float* __restrict__ Bm,
                               float* __restrict__ C,
                               int M, int N, int K,
                               int lda, int ldb, int ldc)
{
    __shared__ float As[GBK][GBM + 4];
    __shared__ float Bs[GBK][GBN + 4];

    const int m0 = blockIdx.y * GBM;
    const int n0 = blockIdx.x * GBN;
    const int tid = threadIdx.x;
    const int tx = tid & 15;
    const int ty = tid >> 4;

    float acc[4][4] = {};

    for (int k0 = 0; k0 < K; k0 += GBK) {
        {
            const int r  = tid >> 2;
            const int kq = (tid & 3) * 4;
            const float4 a = *(const float4*)(A + (long long)(m0 + r) * lda + k0 + kq);
            As[kq + 0][r] = a.x;
            As[kq + 1][r] = a.y;
            As[kq + 2][r] = a.z;
            As[kq + 3][r] = a.w;
            const float4 b = *(const float4*)(Bm + (long long)(n0 + r) * ldb + k0 + kq);
            Bs[kq + 0][r] = b.x;
            Bs[kq + 1][r] = b.y;
            Bs[kq + 2][r] = b.z;
            Bs[kq + 3][r] = b.w;
        }
        __syncthreads();
        #pragma unroll
        for (int k = 0; k < GBK; k++) {
            const float4 a4 = *(const float4*)&As[k][ty * 4];
            const float4 b4 = *(const float4*)&Bs[k][tx * 4];
            const float ar[4] = {a4.x, a4.y, a4.z, a4.w};
            const float br[4] = {b4.x, b4.y, b4.z, b4.w};
            #pragma unroll
            for (int i = 0; i < 4; i++)
                #pragma unroll
                for (int j = 0; j < 4; j++)
                    acc[i][j] += ar[i] * br[j];
        }
        __syncthreads();
    }

    #pragma unroll
    for (int i = 0; i < 4; i++) {
        const int m = m0 + ty * 4 + i;
        float4 o;
        o.x = acc[i][0];
        o.y = acc[i][1];
        o.z = acc[i][2];
        o.w = acc[i][3];
        *(float4*)(C + (long long)m * ldc + n0 + tx * 4) = o;
    }
}

// ---------------- rmsnorm over Q_RANK=768 per row ----------------
__global__ void rmsnorm_kernel(const float* __restrict__ xin,
                               const float* __restrict__ w,
                               float* __restrict__ yout)
{
    const int r = blockIdx.x;
    const int tid = threadIdx.x;
    const float* xr = xin + r * Q_RANKv;
    float s = 0.f;
    #pragma unroll
    for (int i = 0; i < 3; i++) {
        const float v = xr[tid + i * 256];
        s += v * v;
    }
    __shared__ float red[256];
    red[tid] = s;
    __syncthreads();
    for (int o = 128; o > 0; o >>= 1) {
        if (tid < o) red[tid] += red[tid + o];
        __syncthreads();
    }
    const float inv = rsqrtf(red[0] / (float)Q_RANKv + EPSv);
    #pragma unroll
    for (int i = 0; i < 3; i++) {
        const int cc = tid + i * 256;
        yout[r * Q_RANKv + cc] = xr[cc] * inv * w[cc];
    }
}

// ---------------- rope -----------------------------------------------------
__global__ void rope_kernel(float* __restrict__ q, float* __restrict__ kv,
                            const float* __restrict__ fc,
                            const float* __restrict__ fs)
{
    const int bl = blockIdx.x;
    const int l = bl & 31;
    const int tid = threadIdx.x;
    for (int wk = tid; wk < 544; wk += 256) {
        if (wk < 512) {
            const int h = wk >> 5;
            const int j = wk & 31;
            const float cc = fc[l * 32 + j];
            const float ss = fs[l * 32 + j];
            float* p = q + bl * (Hv * QKv) + h * QKv + D_NRv + 2 * j;
            const float xr = p[0], xi = p[1];
            p[0] = xr * cc - xi * ss;
            p[1] = xr * ss + xi * cc;
        } else {
            const int j = wk - 512;
            const float cc = fc[l * 32 + j];
            const float ss = fs[l * 32 + j];
            float* p = kv + bl * KCATv + KV_RANKv + 2 * j;
            const float xr = p[0], xi = p[1];
            p[0] = xr * cc - xi * ss;
            p[1] = xr * ss + xi * cc;
        }
    }
}

// ---------------- build Acat ------------------------------------------------
__global__ void build_acat_kernel(const float* __restrict__ q,
                                  const float* __restrict__ w_kv_up,
                                  float* __restrict__ Acat)
{
    const int bl = blockIdx.x;
    const int h  = blockIdx.y;
    const int b = bl >> 5, l = bl & 31;
    const int row = b * 512 + h * 32 + l;
    const int tid = threadIdx.x;

    __shared__ float qs[D_NRv];
    if (tid < D_NRv) qs[tid] = q[bl * (Hv * QKv) + h * QKv + tid];
    __syncthreads();

    const float* w = w_kv_up + (long long)(h * 256) * KV_RANKv;
    float a0 = 0.f, a1 = 0.f;
    #pragma unroll 4
    for (int d = 0; d < D_NRv; d++) {
        const float qd = qs[d];
        a0 += qd * w[d * KV_RANKv + tid];
        a1 += qd * w[d * KV_RANKv + tid + 256];
    }
    float* drow = Acat + (long long)row * KCATv;
    drow[tid]       = a0;
    drow[tid + 256] = a1;
    if (tid < D_Rv)
        drow[KV_RANKv + tid] = q[bl * (Hv * QKv) + h * QKv + D_NRv + tid];
}

// ---------------- build Kcat ------------------------------------------------
__global__ void build_kcat_kernel(const float* __restrict__ kvc,
                                  const float* __restrict__ krc,
                                  const float* __restrict__ kvfresh,
                                  float* __restrict__ Kcat)
{
    const int t = blockIdx.x;
    const int b = blockIdx.y;
    const int tid = threadIdx.x;
    float* dst = Kcat + ((long long)b * MAXTv + t) * KCATv;
    if (t < STARTv) {
        const float* skv = kvc + ((long long)b * MAXTv + t) * KV_RANKv;
        const float* skr = krc + ((long long)b * MAXTv + t) * D_Rv;
        for (int cc = tid; cc < KCATv; cc += 256)
            dst[cc] = (cc < KV_RANKv) ? skv[cc] : skr[cc - KV_RANKv];
    } else {
        const float* src = kvfresh + (b * Lv + (t - STARTv)) * KCATv;
        for (int cc = tid; cc < KCATv; cc += 256)
            dst[cc] = src[cc];
    }
}

// ---------------- softmax ---------------------------------------------------
__global__ void softmax_kernel(float* __restrict__ scores,
                               const float* __restrict__ mask)
{
    const int id = blockIdx.x;
    const int l = id & 31;
    const int tid = threadIdx.x;
    float* row = scores + (long long)id * MAXTv;
    const float* mrow = mask + l * MAXTv;

    float vals[16];
    float vmax = -3.4e38f;
    #pragma unroll
    for (int i = 0; i < 16; i++) {
        const int t = tid + i * 256;
        const float v = row[t] * SCALEv + mrow[t];
        vals[i] = v;
        vmax = fmaxf(vmax, v);
    }
    __shared__ float red[256];
    red[tid] = vmax;
    __syncthreads();
    for (int o = 128; o > 0; o >>= 1) {
        if (tid < o) red[tid] = fmaxf(red[tid], red[tid + o]);
        __syncthreads();
    }
    const float m = red[0];
    __syncthreads();

    float sum = 0.f;
    #pragma unroll
    for (int i = 0; i < 16; i++) {
        const float e = expf(vals[i] - m);
        vals[i] = e;
        sum += e;
    }
    red[tid] = sum;
    __syncthreads();
    for (int o = 128; o > 0; o >>= 1) {
        if (tid < o) red[tid] += red[tid + o];
        __syncthreads();
    }
    const float inv = 1.0f / red[0];
    #pragma unroll
    for (int i = 0; i < 16; i++)
        row[tid + i * 256] = vals[i] * inv;
}

// ---------------- o through V-up part of W_kv_up ----------------------------
__global__ void o_up_kernel(const float* __restrict__ Oin,
                            const float* __restrict__ w_kv_up,
                            float* __restrict__ o2)
{
    const int bl = blockIdx.x;
    const int h  = blockIdx.y;
    const int b = bl >> 5, l = bl & 31;
    const int tid = threadIdx.x;

    __shared__ float os[KV_RANKv];
    const float* orow = Oin + (long long)(b * 512 + h * 32 + l) * KV_RANKv;
    for (int cc = tid; cc < KV_RANKv; cc += 128)
        os[cc] = orow[cc];
    __syncthreads();

    const float* w = w_kv_up + (long long)(h * 256 + 128 + tid) * KV_RANKv;
    float acc = 0.f;
    #pragma unroll 4
    for (int k = 0; k < KV_RANKv; k += 4) {
        const float4 w4 = *(const float4*)(w + k);
        acc += os[k] * w4.x + os[k + 1] * w4.y + os[k + 2] * w4.z + os[k + 3] * w4.w;
    }
    o2[bl * (Hv * D_Vv) + h * D_Vv + tid] = acc;
}

// ---------------- launch ----------------------------------------------------
extern "C" void kernel_launch(void* const* d_in, const int* in_sizes, int n_in,
                              void* d_out, int out_size)
{
    const float* x         = (const float*)d_in[0];
    const float* freq_cos  = (const float*)d_in[2];
    const float* freq_sin  = (const float*)d_in[3];
    const float* mask      = (const float*)d_in[4];
    const float* kvc       = (const float*)d_in[5];
    const float* krc       = (const float*)d_in[6];
    const float* w_kv_down = (const float*)d_in[7];
    const float* w_q_down  = (const float*)d_in[8];
    const float* rms_q_w   = (const float*)d_in[9];
    const float* w_q_up    = (const float*)d_in[10];
    const float* w_kv_up   = (const float*)d_in[11];
    const float* w_out     = (const float*)d_in[12];
    float* out = (float*)d_out;

    float* qlin = 0;
    float* qdn = 0;
    float* q = 0;
    float* kv = 0;
    float* Acat = 0;
    float* Kcat = 0;
    float* scores = 0;
    float* Obuf = 0;
    float* o2 = 0;
    cudaGetSymbolAddress((void**)&qlin,   g_qlin);
    cudaGetSymbolAddress((void**)&qdn,    g_qdn);
    cudaGetSymbolAddress((void**)&q,      g_q);
    cudaGetSymbolAddress((void**)&kv,     g_kv);
    cudaGetSymbolAddress((void**)&Acat,   g_Acat);
    cudaGetSymbolAddress((void**)&Kcat,   g_Kcat);
    cudaGetSymbolAddress((void**)&scores, g_scores);
    cudaGetSymbolAddress((void**)&Obuf,   g_O);
    cudaGetSymbolAddress((void**)&o2,     g_o2);

    // 1) q_down: (256,768) = x(256,2048) * w_q_down(768,2048)^T   [tensor]
    gemm_tc<true><<<dim3(Q_RANKv / 128, BLv / 128, 1), 256>>>(
        x, w_q_down, qlin, BLv, Q_RANKv, DIMv, DIMv, DIMv, Q_RANKv, 0, 0, 0);

    // 2) kv_down: (256,576) fp32
    gemm_kernel_bt<<<dim3(KCATv / GBN, BLv / GBM, 1), 256>>>(
        x, w_kv_down, kv, BLv, KCATv, DIMv, DIMv, DIMv, KCATv);

    // 3) rmsnorm
    rmsnorm_kernel<<<BLv, 256>>>(qlin, rms_q_w, qdn);

    // 4) q_up: (256,3072)   [tensor]
    gemm_tc<true><<<dim3((Hv * QKv) / 128, BLv / 128, 1), 256>>>(
        qdn, w_q_up, q, BLv, Hv * QKv, Q_RANKv, Q_RANKv, Q_RANKv, Hv * QKv, 0, 0, 0);

    // 5) rope
    rope_kernel<<<BLv, 256>>>(q, kv, freq_cos, freq_sin);

    // 6) Acat
    build_acat_kernel<<<dim3(BLv, Hv), 256>>>(q, w_kv_up, Acat);

    // 7) Kcat
    build_kcat_kernel<<<dim3(MAXTv, Bv), 256>>>(kvc, krc, kv, Kcat);

    // 8) scores = Acat @ Kcat^T, batched: (512,4096,576)   [tensor]
    gemm_tc<true><<<dim3(MAXTv / 128, 512 / 128, Bv), 256>>>(
        Acat, Kcat, scores, 512, MAXTv, KCATv, KCATv, KCATv, MAXTv,
        (long long)512 * KCATv, (long long)MAXTv * KCATv, (long long)512 * MAXTv);

    // 9) softmax
    softmax_kernel<<<Bv * 512, 256>>>(scores, mask);

    // 10) O = P @ Kcat[:, :512], batched (512,512,4096)   [tensor]
    gemm_tc<false><<<dim3(KV_RANKv / 128, 512 / 128, Bv), 256>>>(
        scores, Kcat, Obuf, 512, KV_RANKv, MAXTv, MAXTv, KCATv, KV_RANKv,
        (long long)512 * MAXTv, (long long)MAXTv * KCATv, (long long)512 * KV_RANKv);

    // 11) o2 = O @ W_up_v^T per head
    o_up_kernel<<<dim3(BLv, Hv), 128>>>(Obuf, w_kv_up, o2);

    // 12) out = o2 @ w_out^T : (256,2048,2048)   [tensor]
    gemm_tc<true><<<dim3(DIMv / 128, BLv / 128, 1), 256>>>(
        o2, w_out, out, BLv, DIMv, DIMv, DIMv, DIMv, DIMv, 0, 0, 0);
}

// round 4
// speedup vs baseline: 1.5806x; 1.1569x over previous
#include <cuda_runtime.h>
#include <math.h>
#include <stdint.h>

typedef unsigned short ush;
typedef unsigned int   uin;

// ---------------- problem constants ----------------
#define Bv      8
#define Lv      32
#define BLv     256
#define DIMv    2048
#define KV_RANKv 512
#define Q_RANKv 768
#define Hv      16
#define D_NRv   128
#define D_Rv    64
#define D_Vv    128
#define QKv     192
#define MAXTv   4096
#define STARTv  4064
#define KCATv   576
#define EPSv    1.1920929e-07f
#define SCALEv  0.07216878364870323f

// ---------------- scratch (device globals) ----------------
__device__ float g_qlin  [BLv * Q_RANKv];
__device__ float g_q     [BLv * Hv * QKv];
__device__ float g_kv    [BLv * KCATv];
__device__ float g_scores[(long long)Bv * 512 * MAXTv];
__device__ float g_O     [Bv * 512 * 512];

// bf16 hi/lo operand arrays
__device__ ush g_xh   [BLv * DIMv],        g_xl   [BLv * DIMv];
__device__ ush g_wqdh [Q_RANKv * DIMv],    g_wqdl [Q_RANKv * DIMv];
__device__ ush g_wquh [Hv*QKv * Q_RANKv],  g_wqul [Hv*QKv * Q_RANKv];
__device__ ush g_wouth[DIMv * DIMv],       g_woutl[DIMv * DIMv];
__device__ ush g_qdnh [BLv * Q_RANKv],     g_qdnl [BLv * Q_RANKv];
__device__ ush g_acath[Bv*512 * KCATv],    g_acatl[Bv*512 * KCATv];
__device__ ush g_kcath[(long long)Bv*MAXTv*KCATv], g_kcatl[(long long)Bv*MAXTv*KCATv];
__device__ ush g_kTh  [(long long)Bv*512*MAXTv],   g_kTl  [(long long)Bv*512*MAXTv];
__device__ ush g_ph   [(long long)Bv*512*MAXTv],   g_pl   [(long long)Bv*512*MAXTv];
__device__ ush g_o2h  [BLv * Hv*D_Vv],     g_o2l  [BLv * Hv*D_Vv];

// ---------------- bf16 bit helpers ----------------
__device__ __forceinline__ ush bf16_rn(float x) {
    uin u = __float_as_uint(x);
    uin r = u + 0x7FFFu + ((u >> 16) & 1u);
    return (ush)(r >> 16);
}
__device__ __forceinline__ float bf16_tof(ush h) {
    return __uint_as_float(((uin)h) << 16);
}
__device__ __forceinline__ void splitw(float x, ush* h, ush* l) {
    ush hh = bf16_rn(x);
    *h = hh;
    *l = bf16_rn(x - bf16_tof(hh));
}

__device__ __forceinline__ void ldmx4(uin* r, const void* p) {
    uin a = (uin)__cvta_generic_to_shared(p);
    asm volatile("ldmatrix.sync.aligned.m8n8.x4.shared.b16 {%0,%1,%2,%3}, [%4];"
                 : "=r"(r[0]), "=r"(r[1]), "=r"(r[2]), "=r"(r[3]) : "r"(a));
}
__device__ __forceinline__ void mma16816(float* c, const uin* a, uin b0, uin b1) {
    asm volatile(
        "mma.sync.aligned.m16n8k16.row.col.f32.bf16.bf16.f32 "
        "{%0,%1,%2,%3},{%4,%5,%6,%7},{%8,%9},{%0,%1,%2,%3};\n"
        : "+f"(c[0]), "+f"(c[1]), "+f"(c[2]), "+f"(c[3])
        : "r"(a[0]), "r"(a[1]), "r"(a[2]), "r"(a[3]), "r"(b0), "r"(b1));
}
__device__ __forceinline__ void cpa16(void* s, const void* g) {
    uin sa = (uin)__cvta_generic_to_shared(s);
    asm volatile("cp.async.cg.shared.global [%0], [%1], 16;" :: "r"(sa), "l"(g));
}

// ====================================================================
//  bf16 hi/lo tensor-core GEMM, cp.async double-buffered.
//  C[M,N](fp32) = (Ah+Al)[M,K] * (Bh+Bl)[N,K]^T  (3-term split product)
//  M%128==0, N%128==0, K%32==0.
//  smem: 2 stages x 4 tiles x 128 rows x 40 ush (80B stride) = 80KB dynamic
// ====================================================================
#define TILE_USH  5120    // 128*40
#define STAGE_USH 20480   // 4 tiles

__device__ __forceinline__ void stage_load(ush* sm,
        const ush* Ahg, const ush* Alg, const ush* Bhg, const ush* Blg,
        int m0, int n0, int k0, int lda, int ldb, int tid)
{
    const int row = tid >> 1;
    const int c2  = (tid & 1) * 2;
    #pragma unroll
    for (int j = 0; j < 2; j++) {
        const int col = (c2 + j) * 8;
        const long long aoff = (long long)(m0 + row) * lda + k0 + col;
        const long long boff = (long long)(n0 + row) * ldb + k0 + col;
        ush* d = sm + row * 40 + col;
        cpa16(d,                 Ahg + aoff);
        cpa16(d + TILE_USH,      Alg + aoff);
        cpa16(d + 2 * TILE_USH,  Bhg + boff);
        cpa16(d + 3 * TILE_USH,  Blg + boff);
    }
}

__global__ __launch_bounds__(256, 2)
void gemm_tc2(const ush* __restrict__ Ahg, const ush* __restrict__ Alg,
              const ush* __restrict__ Bhg, const ush* __restrict__ Blg,
              float* __restrict__ C,
              int M, int N, int K, int lda, int ldb, int ldc,
              long long sA, long long sB, long long sC)
{
    extern __shared__ ush dsm[];

    const int bz = blockIdx.z;
    Ahg += bz * sA;  Alg += bz * sA;
    Bhg += bz * sB;  Blg += bz * sB;
    C   += bz * sC;

    const int m0 = blockIdx.y * 128;
    const int n0 = blockIdx.x * 128;
    const int tid  = threadIdx.x;
    const int wid  = tid >> 5;
    const int lane = tid & 31;
    const int wm = (wid & 1) * 64;
    const int wn = (wid >> 1) * 32;
    const int lr = lane & 7;
    const int lg = lane >> 3;

    float c[4][4][4];
    #pragma unroll
    for (int i = 0; i < 4; i++)
        #pragma unroll
        for (int j = 0; j < 4; j++)
            #pragma unroll
            for (int t = 0; t < 4; t++)
                c[i][j][t] = 0.0f;

    const int KT = K >> 5;

    stage_load(dsm, Ahg, Alg, Bhg, Blg, m0, n0, 0, lda, ldb, tid);
    asm volatile("cp.async.commit_group;");

    for (int kt = 0; kt < KT; kt++) {
        const ush* cur = dsm + (kt & 1) * STAGE_USH;
        if (kt + 1 < KT) {
            stage_load(dsm + ((kt + 1) & 1) * STAGE_USH,
                       Ahg, Alg, Bhg, Blg, m0, n0, (kt + 1) << 5, lda, ldb, tid);
            asm volatile("cp.async.commit_group;");
            asm volatile("cp.async.wait_group 1;");
        } else {
            asm volatile("cp.async.wait_group 0;");
        }
        __syncthreads();

        const ush* sAh = cur;
        const ush* sAl = cur + TILE_USH;
        const ush* sBh = cur + 2 * TILE_USH;
        const ush* sBl = cur + 3 * TILE_USH;

        #pragma unroll
        for (int kk = 0; kk < 32; kk += 16) {
            uin bh[2][4], bl[2][4];
            #pragma unroll
            for (int j2 = 0; j2 < 2; j2++) {
                const int nrow = wn + j2 * 16 + lr + ((lg & 2) << 2);
                const int kcol = kk + ((lg & 1) << 3);
                ldmx4(bh[j2], sBh + nrow * 40 + kcol);
                ldmx4(bl[j2], sBl + nrow * 40 + kcol);
            }
            #pragma unroll
            for (int im = 0; im < 4; im++) {
                uin ah[4], al[4];
                const int mrow = wm + im * 16 + lr + ((lg & 1) << 3);
                const int kcol = kk + ((lg & 2) << 2);
                ldmx4(ah, sAh + mrow * 40 + kcol);
                ldmx4(al, sAl + mrow * 40 + kcol);
                #pragma unroll
                for (int j2 = 0; j2 < 2; j2++) {
                    #pragma unroll
                    for (int t = 0; t < 2; t++) {
                        const int jn = j2 * 2 + t;
                        mma16816(c[im][jn], ah, bh[j2][t * 2], bh[j2][t * 2 + 1]);
                        mma16816(c[im][jn], ah, bl[j2][t * 2], bl[j2][t * 2 + 1]);
                        mma16816(c[im][jn], al, bh[j2][t * 2], bh[j2][t * 2 + 1]);
                    }
                }
            }
        }
        __syncthreads();
    }

    #pragma unroll
    for (int im = 0; im < 4; im++) {
        const int row = m0 + wm + im * 16 + (lane >> 2);
        #pragma unroll
        for (int jn = 0; jn < 4; jn++) {
            const int col = n0 + wn + jn * 8 + (lane & 3) * 2;
            float2 v0, v1;
            v0.x = c[im][jn][0];
            v0.y = c[im][jn][1];
            v1.x = c[im][jn][2];
            v1.y = c[im][jn][3];
            *(float2*)(C + (long long)row * ldc + col)       = v0;
            *(float2*)(C + (long long)(row + 8) * ldc + col) = v1;
        }
    }
}

// ---------------- fp32 split converter (x, weights) ----------------
__global__ void convert_split(const float* __restrict__ src,
                              ush* __restrict__ h, ush* __restrict__ l)
{
    const int i = blockIdx.x * blockDim.x + threadIdx.x;  // one per 8 elts
    const float4 a = *(const float4*)(src + i * 8);
    const float4 b = *(const float4*)(src + i * 8 + 4);
    ush hh[8], ll[8];
    splitw(a.x, &hh[0], &ll[0]); splitw(a.y, &hh[1], &ll[1]);
    splitw(a.z, &hh[2], &ll[2]); splitw(a.w, &hh[3], &ll[3]);
    splitw(b.x, &hh[4], &ll[4]); splitw(b.y, &hh[5], &ll[5]);
    splitw(b.z, &hh[6], &ll[6]); splitw(b.w, &hh[7], &ll[7]);
    uint4 ph, pl;
    ph.x = (uin)hh[0] | ((uin)hh[1] << 16);
    ph.y = (uin)hh[2] | ((uin)hh[3] << 16);
    ph.z = (uin)hh[4] | ((uin)hh[5] << 16);
    ph.w = (uin)hh[6] | ((uin)hh[7] << 16);
    pl.x = (uin)ll[0] | ((uin)ll[1] << 16);
    pl.y = (uin)ll[2] | ((uin)ll[3] << 16);
    pl.z = (uin)ll[4] | ((uin)ll[5] << 16);
    pl.w = (uin)ll[6] | ((uin)ll[7] << 16);
    *(uint4*)(h + i * 8) = ph;
    *(uint4*)(l + i * 8) = pl;
}

// ---------------- fp32 tiled SGEMM (kv_down, N=576) ----------------
#define GBM 64
#define GBN 64
#define GBK 16

__global__ void gemm_kernel_bt(const float* __restrict__ A,
                               const float* __restrict__ Bm,
                               float* __restrict__ C,
                               int M, int N, int K,
                               int lda, int ldb, int ldc)
{
    __shared__ float As[GBK][GBM + 4];
    __shared__ float Bs[GBK][GBN + 4];

    const int m0 = blockIdx.y * GBM;
    const int n0 = blockIdx.x * GBN;
    const int tid = threadIdx.x;
    const int tx = tid & 15;
    const int ty = tid >> 4;

    float acc[4][4] = {};

    for (int k0 = 0; k0 < K; k0 += GBK) {
        {
            const int r  = tid >> 2;
            const int kq = (tid & 3) * 4;
            const float4 a = *(const float4*)(A + (long long)(m0 + r) * lda + k0 + kq);
            As[kq + 0][r] = a.x; As[kq + 1][r] = a.y;
            As[kq + 2][r] = a.z; As[kq + 3][r] = a.w;
            const float4 b = *(const float4*)(Bm + (long long)(n0 + r) * ldb + k0 + kq);
            Bs[kq + 0][r] = b.x; Bs[kq + 1][r] = b.y;
            Bs[kq + 2][r] = b.z; Bs[kq + 3][r] = b.w;
        }
        __syncthreads();
        #pragma unroll
        for (int k = 0; k < GBK; k++) {
            const float4 a4 = *(const float4*)&As[k][ty * 4];
            const float4 b4 = *(const float4*)&Bs[k][tx * 4];
            const float ar[4] = {a4.x, a4.y, a4.z, a4.w};
            const float br[4] = {b4.x, b4.y, b4.z, b4.w};
            #pragma unroll
            for (int i = 0; i < 4; i++)
                #pragma unroll
                for (int j = 0; j < 4; j++)
                    acc[i][j] += ar[i] * br[j];
        }
        __syncthreads();
    }

    #pragma unroll
    for (int i = 0; i < 4; i++) {
        const int m = m0 + ty * 4 + i;
        float4 o;
        o.x = acc[i][0]; o.y = acc[i][1]; o.z = acc[i][2]; o.w = acc[i][3];
        *(float4*)(C + (long long)m * ldc + n0 + tx * 4) = o;
    }
}

// ---------------- rmsnorm -> bf16 hi/lo ----------------
__global__ void rmsnorm_kernel(const float* __restrict__ xin,
                               const float* __restrict__ w,
                               ush* __restrict__ yh, ush* __restrict__ yl)
{
    const int r = blockIdx.x;
    const int tid = threadIdx.x;
    const float* xr = xin + r * Q_RANKv;
    float s = 0.f;
    #pragma unroll
    for (int i = 0; i < 3; i++) {
        const float v = xr[tid + i * 256];
        s += v * v;
    }
    __shared__ float red[256];
    red[tid] = s;
    __syncthreads();
    for (int o = 128; o > 0; o >>= 1) {
        if (tid < o) red[tid] += red[tid + o];
        __syncthreads();
    }
    const float inv = rsqrtf(red[0] / (float)Q_RANKv + EPSv);
    #pragma unroll
    for (int i = 0; i < 3; i++) {
        const int cc = tid + i * 256;
        const float v = xr[cc] * inv * w[cc];
        ush h, l;
        splitw(v, &h, &l);
        yh[r * Q_RANKv + cc] = h;
        yl[r * Q_RANKv + cc] = l;
    }
}

// ---------------- rope (fp32 in place) ----------------
__global__ void rope_kernel(float* __restrict__ q, float* __restrict__ kv,
                            const float* __restrict__ fc,
                            const float* __restrict__ fs)
{
    const int bl = blockIdx.x;
    const int l = bl & 31;
    const int tid = threadIdx.x;
    for (int wk = tid; wk < 544; wk += 256) {
        if (wk < 512) {
            const int h = wk >> 5;
            const int j = wk & 31;
            const float cc = fc[l * 32 + j];
            const float ss = fs[l * 32 + j];
            float* p = q + bl * (Hv * QKv) + h * QKv + D_NRv + 2 * j;
            const float xr = p[0], xi = p[1];
            p[0] = xr * cc - xi * ss;
            p[1] = xr * ss + xi * cc;
        } else {
            const int j = wk - 512;
            const float cc = fc[l * 32 + j];
            const float ss = fs[l * 32 + j];
            float* p = kv + bl * KCATv + KV_RANKv + 2 * j;
            const float xr = p[0], xi = p[1];
            p[0] = xr * cc - xi * ss;
            p[1] = xr * ss + xi * cc;
        }
    }
}

// ---------------- build Acat -> bf16 hi/lo ----------------
__global__ void build_acat_kernel(const float* __restrict__ q,
                                  const float* __restrict__ w_kv_up,
                                  ush* __restrict__ Ah, ush* __restrict__ Al)
{
    const int bl = blockIdx.x;
    const int h  = blockIdx.y;
    const int b = bl >> 5, l = bl & 31;
    const int row = b * 512 + h * 32 + l;
    const int tid = threadIdx.x;

    __shared__ float qs[D_NRv];
    if (tid < D_NRv) qs[tid] = q[bl * (Hv * QKv) + h * QKv + tid];
    __syncthreads();

    const float* w = w_kv_up + (long long)(h * 256) * KV_RANKv;
    float a0 = 0.f, a1 = 0.f;
    #pragma unroll 4
    for (int d = 0; d < D_NRv; d++) {
        const float qd = qs[d];
        a0 += qd * w[d * KV_RANKv + tid];
        a1 += qd * w[d * KV_RANKv + tid + 256];
    }
    ush hh, ll;
    const long long base = (long long)row * KCATv;
    splitw(a0, &hh, &ll);
    Ah[base + tid] = hh;       Al[base + tid] = ll;
    splitw(a1, &hh, &ll);
    Ah[base + tid + 256] = hh; Al[base + tid + 256] = ll;
    if (tid < D_Rv) {
        const float v = q[bl * (Hv * QKv) + h * QKv + D_NRv + tid];
        splitw(v, &hh, &ll);
        Ah[base + KV_RANKv + tid] = hh;
        Al[base + KV_RANKv + tid] = ll;
    }
}

// ---------------- build Kcat -> bf16 hi/lo ----------------
__global__ void build_kcat_kernel(const float* __restrict__ kvc,
                                  const float* __restrict__ krc,
                                  const float* __restrict__ kvfresh,
                                  ush* __restrict__ Kh, ush* __restrict__ Kl)
{
    const int t = blockIdx.x;
    const int b = blockIdx.y;
    const int tid = threadIdx.x;
    const long long base = ((long long)b * MAXTv + t) * KCATv;
    if (t < STARTv) {
        const float* skv = kvc + ((long long)b * MAXTv + t) * KV_RANKv;
        const float* skr = krc + ((long long)b * MAXTv + t) * D_Rv;
        for (int cc = tid; cc < KCATv; cc += 256) {
            const float v = (cc < KV_RANKv) ? skv[cc] : skr[cc - KV_RANKv];
            ush h, l;
            splitw(v, &h, &l);
            Kh[base + cc] = h;
            Kl[base + cc] = l;
        }
    } else {
        const float* src = kvfresh + (b * Lv + (t - STARTv)) * KCATv;
        for (int cc = tid; cc < KCATv; cc += 256) {
            ush h, l;
            splitw(src[cc], &h, &l);
            Kh[base + cc] = h;
            Kl[base + cc] = l;
        }
    }
}

// ---------------- transpose Kcat[:, :512] -> KcatT (both arrays) ----------
__global__ void transpose_kcat(const ush* __restrict__ Kh, const ush* __restrict__ Kl,
                               ush* __restrict__ Th, ush* __restrict__ Tl)
{
    __shared__ ush th[32][33];
    __shared__ ush tl[32][33];
    const int b = blockIdx.z;
    const int t0 = blockIdx.x * 32;
    const int c0 = blockIdx.y * 32;
    const int tx = threadIdx.x;
    const int ty = threadIdx.y;  // 0..7
    #pragma unroll
    for (int i = 0; i < 32; i += 8) {
        const long long src = ((long long)b * MAXTv + t0 + ty + i) * KCATv + c0 + tx;
        th[ty + i][tx] = Kh[src];
        tl[ty + i][tx] = Kl[src];
    }
    __syncthreads();
    #pragma unroll
    for (int i = 0; i < 32; i += 8) {
        const long long dst = ((long long)b * 512 + c0 + ty + i) * MAXTv + t0 + tx;
        Th[dst] = th[tx][ty + i];
        Tl[dst] = tl[tx][ty + i];
    }
}

// ---------------- softmax -> P bf16 hi/lo ----------------
__global__ void softmax_kernel(const float* __restrict__ scores,
                               const float* __restrict__ mask,
                               ush* __restrict__ Ph, ush* __restrict__ Pl)
{
    const int id = blockIdx.x;           // b*512 + h*32 + l
    const int l = id & 31;
    const int tid = threadIdx.x;
    const float* row = scores + (long long)id * MAXTv;
    const float* mrow = mask + l * MAXTv;
    const int base = tid * 16;

    float vals[16];
    float vmax = -3.4e38f;
    #pragma unroll
    for (int i = 0; i < 16; i += 4) {
        const float4 v4 = *(const float4*)(row + base + i);
        const float4 m4 = *(const float4*)(mrow + base + i);
        vals[i + 0] = v4.x * SCALEv + m4.x;
        vals[i + 1] = v4.y * SCALEv + m4.y;
        vals[i + 2] = v4.z * SCALEv + m4.z;
        vals[i + 3] = v4.w * SCALEv + m4.w;
        vmax = fmaxf(vmax, fmaxf(fmaxf(vals[i], vals[i + 1]),
                                 fmaxf(vals[i + 2], vals[i + 3])));
    }
    __shared__ float red[256];
    red[tid] = vmax;
    __syncthreads();
    for (int o = 128; o > 0; o >>= 1) {
        if (tid < o) red[tid] = fmaxf(red[tid], red[tid + o]);
        __syncthreads();
    }
    const float m = red[0];
    __syncthreads();

    float sum = 0.f;
    #pragma unroll
    for (int i = 0; i < 16; i++) {
        const float e = expf(vals[i] - m);
        vals[i] = e;
        sum += e;
    }
    red[tid] = sum;
    __syncthreads();
    for (int o = 128; o > 0; o >>= 1) {
        if (tid < o) red[tid] += red[tid + o];
        __syncthreads();
    }
    const float inv = 1.0f / red[0];

    uin wh[8], wl[8];
    #pragma unroll
    for (int i = 0; i < 8; i++) {
        ush h0, l0, h1, l1;
        splitw(vals[2 * i]     * inv, &h0, &l0);
        splitw(vals[2 * i + 1] * inv, &h1, &l1);
        wh[i] = (uin)h0 | ((uin)h1 << 16);
        wl[i] = (uin)l0 | ((uin)l1 << 16);
    }
    const long long off = (long long)id * MAXTv + base;
    *(uint4*)(Ph + off)     = make_uint4(wh[0], wh[1], wh[2], wh[3]);
    *(uint4*)(Ph + off + 8) = make_uint4(wh[4], wh[5], wh[6], wh[7]);
    *(uint4*)(Pl + off)     = make_uint4(wl[0], wl[1], wl[2], wl[3]);
    *(uint4*)(Pl + off + 8) = make_uint4(wl[4], wl[5], wl[6], wl[7]);
}

// ---------------- o_up -> o2 bf16 hi/lo ----------------
__global__ void o_up_kernel(const float* __restrict__ Oin,
                            const float* __restrict__ w_kv_up,
                            ush* __restrict__ o2h, ush* __restrict__ o2l)
{
    const int bl = blockIdx.x;
    const int h  = blockIdx.y;
    const int b = bl >> 5, l = bl & 31;
    const int tid = threadIdx.x;

    __shared__ float os[KV_RANKv];
    const float* orow = Oin + (long long)(b * 512 + h * 32 + l) * KV_RANKv;
    for (int cc = tid; cc < KV_RANKv; cc += 128)
        os[cc] = orow[cc];
    __syncthreads();

    const float* w = w_kv_up + (long long)(h * 256 + 128 + tid) * KV_RANKv;
    float acc = 0.f;
    #pragma unroll 4
    for (int k = 0; k < KV_RANKv; k += 4) {
        const float4 w4 = *(const float4*)(w + k);
        acc += os[k] * w4.x + os[k + 1] * w4.y + os[k + 2] * w4.z + os[k + 3] * w4.w;
    }
    ush hh, ll;
    splitw(acc, &hh, &ll);
    o2h[bl * (Hv * D_Vv) + h * D_Vv + tid] = hh;
    o2l[bl * (Hv * D_Vv) + h * D_Vv + tid] = ll;
}

// ---------------- launch ----------------------------------------------------
#define SMEM_GT2 81920

extern "C" void kernel_launch(void* const* d_in, const int* in_sizes, int n_in,
                              void* d_out, int out_size)
{
    const float* x         = (const float*)d_in[0];
    const float* freq_cos  = (const float*)d_in[2];
    const float* freq_sin  = (const float*)d_in[3];
    const float* mask      = (const float*)d_in[4];
    const float* kvc       = (const float*)d_in[5];
    const float* krc       = (const float*)d_in[6];
    const float* w_kv_down = (const float*)d_in[7];
    const float* w_q_down  = (const float*)d_in[8];
    const float* rms_q_w   = (const float*)d_in[9];
    const float* w_q_up    = (const float*)d_in[10];
    const float* w_kv_up   = (const float*)d_in[11];
    const float* w_out     = (const float*)d_in[12];
    float* out = (float*)d_out;

    cudaFuncSetAttribute(gemm_tc2, cudaFuncAttributeMaxDynamicSharedMemorySize,
                         SMEM_GT2);

    float* qlin = 0;   float* q = 0;    float* kv = 0;
    float* scores = 0; float* Obuf = 0;
    ush *xh=0,*xl=0,*wqdh=0,*wqdl=0,*wquh=0,*wqul=0,*wouth=0,*woutl=0;
    ush *qdnh=0,*qdnl=0,*acath=0,*acatl=0,*kcath=0,*kcatl=0;
    ush *kTh=0,*kTl=0,*ph=0,*pl=0,*o2h=0,*o2l=0;

    cudaGetSymbolAddress((void**)&qlin,   g_qlin);
    cudaGetSymbolAddress((void**)&q,      g_q);
    cudaGetSymbolAddress((void**)&kv,     g_kv);
    cudaGetSymbolAddress((void**)&scores, g_scores);
    cudaGetSymbolAddress((void**)&Obuf,   g_O);
    cudaGetSymbolAddress((void**)&xh,     g_xh);
    cudaGetSymbolAddress((void**)&xl,     g_xl);
    cudaGetSymbolAddress((void**)&wqdh,   g_wqdh);
    cudaGetSymbolAddress((void**)&wqdl,   g_wqdl);
    cudaGetSymbolAddress((void**)&wquh,   g_wquh);
    cudaGetSymbolAddress((void**)&wqul,   g_wqul);
    cudaGetSymbolAddress((void**)&wouth,  g_wouth);
    cudaGetSymbolAddress((void**)&woutl,  g_woutl);
    cudaGetSymbolAddress((void**)&qdnh,   g_qdnh);
    cudaGetSymbolAddress((void**)&qdnl,   g_qdnl);
    cudaGetSymbolAddress((void**)&acath,  g_acath);
    cudaGetSymbolAddress((void**)&acatl,  g_acatl);
    cudaGetSymbolAddress((void**)&kcath,  g_kcath);
    cudaGetSymbolAddress((void**)&kcatl,  g_kcatl);
    cudaGetSymbolAddress((void**)&kTh,    g_kTh);
    cudaGetSymbolAddress((void**)&kTl,    g_kTl);
    cudaGetSymbolAddress((void**)&ph,     g_ph);
    cudaGetSymbolAddress((void**)&pl,     g_pl);
    cudaGetSymbolAddress((void**)&o2h,    g_o2h);
    cudaGetSymbolAddress((void**)&o2l,    g_o2l);

    // 0) pre-split x and weights
    convert_split<<<(BLv * DIMv) / 8 / 256, 256>>>(x, xh, xl);
    convert_split<<<(Q_RANKv * DIMv) / 8 / 256, 256>>>(w_q_down, wqdh, wqdl);
    convert_split<<<(Hv * QKv * Q_RANKv) / 8 / 256, 256>>>(w_q_up, wquh, wqul);
    convert_split<<<(DIMv * DIMv) / 8 / 256, 256>>>(w_out, wouth, woutl);

    // 1) q_down: (256,768,K=2048)
    gemm_tc2<<<dim3(Q_RANKv / 128, BLv / 128, 1), 256, SMEM_GT2>>>(
        xh, xl, wqdh, wqdl, qlin, BLv, Q_RANKv, DIMv, DIMv, DIMv, Q_RANKv, 0, 0, 0);

    // 2) kv_down fp32: (256,576,2048)
    gemm_kernel_bt<<<dim3(KCATv / GBN, BLv / GBM, 1), 256>>>(
        x, w_kv_down, kv, BLv, KCATv, DIMv, DIMv, DIMv, KCATv);

    // 3) rmsnorm -> qdn hi/lo
    rmsnorm_kernel<<<BLv, 256>>>(qlin, rms_q_w, qdnh, qdnl);

    // 4) q_up: (256,3072,768)
    gemm_tc2<<<dim3((Hv * QKv) / 128, BLv / 128, 1), 256, SMEM_GT2>>>(
        qdnh, qdnl, wquh, wqul, q, BLv, Hv * QKv, Q_RANKv,
        Q_RANKv, Q_RANKv, Hv * QKv, 0, 0, 0);

    // 5) rope
    rope_kernel<<<BLv, 256>>>(q, kv, freq_cos, freq_sin);

    // 6) Acat hi/lo
    build_acat_kernel<<<dim3(BLv, Hv), 256>>>(q, w_kv_up, acath, acatl);

    // 7) Kcat hi/lo
    build_kcat_kernel<<<dim3(MAXTv, Bv), 256>>>(kvc, krc, kv, kcath, kcatl);

    // 7b) KcatT hi/lo
    transpose_kcat<<<dim3(MAXTv / 32, 512 / 32, Bv), dim3(32, 8)>>>(
        kcath, kcatl, kTh, kTl);

    // 8) scores: batched (512,4096,576)
    gemm_tc2<<<dim3(MAXTv / 128, 512 / 128, Bv), 256, SMEM_GT2>>>(
        acath, acatl, kcath, kcatl, scores, 512, MAXTv, KCATv,
        KCATv, KCATv, MAXTv,
        (long long)512 * KCATv, (long long)MAXTv * KCATv, (long long)512 * MAXTv);

    // 9) softmax -> P hi/lo
    softmax_kernel<<<Bv * 512, 256>>>(scores, mask, ph, pl);

    // 10) O = P @ KcatT^T: batched (512,512,4096)
    gemm_tc2<<<dim3(KV_RANKv / 128, 512 / 128, Bv), 256, SMEM_GT2>>>(
        ph, pl, kTh, kTl, Obuf, 512, KV_RANKv, MAXTv,
        MAXTv, MAXTv, KV_RANKv,
        (long long)512 * MAXTv, (long long)512 * MAXTv, (long long)512 * KV_RANKv);

    // 11) o2 hi/lo
    o_up_kernel<<<dim3(BLv, Hv), 128>>>(Obuf, w_kv_up, o2h, o2l);

    // 12) out: (256,2048,2048)
    gemm_tc2<<<dim3(DIMv / 128, BLv / 128, 1), 256, SMEM_GT2>>>(
        o2h, o2l, wouth, woutl, out, BLv, DIMv, DIMv,
        DIMv, DIMv, DIMv, 0, 0, 0);
}

// round 6
// speedup vs baseline: 2.0508x; 1.2974x over previous
#include <cuda_runtime.h>
#include <math.h>
#include <stdint.h>

typedef unsigned short ush;
typedef unsigned int   uin;

// ---------------- problem constants ----------------
#define Bv      8
#define Lv      32
#define BLv     256
#define DIMv    2048
#define KV_RANKv 512
#define Q_RANKv 768
#define Hv      16
#define D_NRv   128
#define D_Rv    64
#define D_Vv    128
#define QKv     192
#define MAXTv   4096
#define STARTv  4064
#define KCATv   576
#define KVPADv  640
#define EPSv    1.1920929e-07f
#define SCALEv  0.07216878364870323f

// ---------------- scratch (device globals) ----------------
__device__ float g_qlin  [BLv * Q_RANKv];
__device__ float g_q     [BLv * Hv * QKv];
__device__ float g_kvpad [BLv * KVPADv];
__device__ float g_scores[(long long)Bv * 512 * MAXTv];
__device__ float g_O     [Bv * 512 * 512];
__device__ float g_part  [Bv * 4 * 512 * 512];    // split-K partials (max 8.4M floats)

__device__ ush g_xh   [BLv * DIMv],        g_xl   [BLv * DIMv];
__device__ ush g_wqdh [Q_RANKv * DIMv],    g_wqdl [Q_RANKv * DIMv];
__device__ ush g_wkvh [KVPADv * DIMv],     g_wkvl [KVPADv * DIMv];
__device__ ush g_wquh [Hv*QKv * Q_RANKv],  g_wqul [Hv*QKv * Q_RANKv];
__device__ ush g_wouth[DIMv * DIMv],       g_woutl[DIMv * DIMv];
__device__ ush g_qdnh [BLv * Q_RANKv],     g_qdnl [BLv * Q_RANKv];
__device__ ush g_acath[Bv*512 * KCATv],    g_acatl[Bv*512 * KCATv];
__device__ ush g_kcath[(long long)Bv*MAXTv*KCATv], g_kcatl[(long long)Bv*MAXTv*KCATv];
__device__ ush g_kTh  [(long long)Bv*512*MAXTv],   g_kTl  [(long long)Bv*512*MAXTv];
__device__ ush g_ph   [(long long)Bv*512*MAXTv],   g_pl   [(long long)Bv*512*MAXTv];
__device__ ush g_o2h  [BLv * Hv*D_Vv],     g_o2l  [BLv * Hv*D_Vv];

// ---------------- bf16 bit helpers ----------------
__device__ __forceinline__ ush bf16_rn(float x) {
    uin u = __float_as_uint(x);
    uin r = u + 0x7FFFu + ((u >> 16) & 1u);
    return (ush)(r >> 16);
}
__device__ __forceinline__ float bf16_tof(ush h) {
    return __uint_as_float(((uin)h) << 16);
}
__device__ __forceinline__ void splitw(float x, ush* h, ush* l) {
    ush hh = bf16_rn(x);
    *h = hh;
    *l = bf16_rn(x - bf16_tof(hh));
}

__device__ __forceinline__ void ldmx4(uin* r, const void* p) {
    uin a = (uin)__cvta_generic_to_shared(p);
    asm volatile("ldmatrix.sync.aligned.m8n8.x4.shared.b16 {%0,%1,%2,%3}, [%4];"
                 : "=r"(r[0]), "=r"(r[1]), "=r"(r[2]), "=r"(r[3]) : "r"(a));
}
__device__ __forceinline__ void mma16816(float* c, const uin* a, uin b0, uin b1) {
    asm volatile(
        "mma.sync.aligned.m16n8k16.row.col.f32.bf16.bf16.f32 "
        "{%0,%1,%2,%3},{%4,%5,%6,%7},{%8,%9},{%0,%1,%2,%3};\n"
        : "+f"(c[0]), "+f"(c[1]), "+f"(c[2]), "+f"(c[3])
        : "r"(a[0]), "r"(a[1]), "r"(a[2]), "r"(a[3]), "r"(b0), "r"(b1));
}
__device__ __forceinline__ void cpa16(void* s, const void* g) {
    uin sa = (uin)__cvta_generic_to_shared(s);
    asm volatile("cp.async.cg.shared.global [%0], [%1], 16;" :: "r"(sa), "l"(g));
}

// ====================================================================
//  bf16 hi/lo tensor-core GEMM, cp.async double-buffered, split-K.
//  C[M,N](fp32) = (Ah+Al)[M,K] * (Bh+Bl)[N,K]^T
//  blockIdx.z = batch * KS + kslice; each slice covers KL of K.
//  If KS>1, C is a partial buffer indexed [batch][kslice][M*N].
// ====================================================================
#define TILE_USH  5120
#define STAGE_USH 20480
#define SMEM_GT2  81920

__device__ __forceinline__ void stage_load(ush* sm,
        const ush* Ahg, const ush* Alg, const ush* Bhg, const ush* Blg,
        int m0, int n0, int k0, int lda, int ldb, int tid)
{
    const int row = tid >> 1;
    const int c2  = (tid & 1) * 2;
    #pragma unroll
    for (int j = 0; j < 2; j++) {
        const int col = (c2 + j) * 8;
        const long long aoff = (long long)(m0 + row) * lda + k0 + col;
        const long long boff = (long long)(n0 + row) * ldb + k0 + col;
        ush* d = sm + row * 40 + col;
        cpa16(d,                 Ahg + aoff);
        cpa16(d + TILE_USH,      Alg + aoff);
        cpa16(d + 2 * TILE_USH,  Bhg + boff);
        cpa16(d + 3 * TILE_USH,  Blg + boff);
    }
}

__global__ __launch_bounds__(256, 2)
void gemm_tc2(const ush* __restrict__ Ahg, const ush* __restrict__ Alg,
              const ush* __restrict__ Bhg, const ush* __restrict__ Blg,
              float* __restrict__ C,
              int M, int N, int lda, int ldb, int ldc,
              long long sA, long long sB, long long sC,
              int KS, int KL)
{
    extern __shared__ ush dsm[];

    const int bz = blockIdx.z;
    const int batch = bz / KS;
    const int ks    = bz - batch * KS;
    Ahg += batch * sA + (long long)ks * KL;
    Alg += batch * sA + (long long)ks * KL;
    Bhg += batch * sB + (long long)ks * KL;
    Blg += batch * sB + (long long)ks * KL;
    C   += (long long)bz * sC;

    const int m0 = blockIdx.y * 128;
    const int n0 = blockIdx.x * 128;
    const int tid  = threadIdx.x;
    const int wid  = tid >> 5;
    const int lane = tid & 31;
    const int wm = (wid & 1) * 64;
    const int wn = (wid >> 1) * 32;
    const int lr = lane & 7;
    const int lg = lane >> 3;

    float c[4][4][4];
    #pragma unroll
    for (int i = 0; i < 4; i++)
        #pragma unroll
        for (int j = 0; j < 4; j++)
            #pragma unroll
            for (int t = 0; t < 4; t++)
                c[i][j][t] = 0.0f;

    const int KT = KL >> 5;

    stage_load(dsm, Ahg, Alg, Bhg, Blg, m0, n0, 0, lda, ldb, tid);
    asm volatile("cp.async.commit_group;");

    for (int kt = 0; kt < KT; kt++) {
        const ush* cur = dsm + (kt & 1) * STAGE_USH;
        if (kt + 1 < KT) {
            stage_load(dsm + ((kt + 1) & 1) * STAGE_USH,
                       Ahg, Alg, Bhg, Blg, m0, n0, (kt + 1) << 5, lda, ldb, tid);
            asm volatile("cp.async.commit_group;");
            asm volatile("cp.async.wait_group 1;");
        } else {
            asm volatile("cp.async.wait_group 0;");
        }
        __syncthreads();

        const ush* sAh = cur;
        const ush* sAl = cur + TILE_USH;
        const ush* sBh = cur + 2 * TILE_USH;
        const ush* sBl = cur + 3 * TILE_USH;

        #pragma unroll
        for (int kk = 0; kk < 32; kk += 16) {
            uin bh[2][4], bl[2][4];
            #pragma unroll
            for (int j2 = 0; j2 < 2; j2++) {
                const int nrow = wn + j2 * 16 + lr + ((lg & 2) << 2);
                const int kcol = kk + ((lg & 1) << 3);
                ldmx4(bh[j2], sBh + nrow * 40 + kcol);
                ldmx4(bl[j2], sBl + nrow * 40 + kcol);
            }
            #pragma unroll
            for (int im = 0; im < 4; im++) {
                uin ah[4], al[4];
                const int mrow = wm + im * 16 + lr + ((lg & 1) << 3);
                const int kcol = kk + ((lg & 2) << 2);
                ldmx4(ah, sAh + mrow * 40 + kcol);
                ldmx4(al, sAl + mrow * 40 + kcol);
                #pragma unroll
                for (int j2 = 0; j2 < 2; j2++) {
                    #pragma unroll
                    for (int t = 0; t < 2; t++) {
                        const int jn = j2 * 2 + t;
                        mma16816(c[im][jn], ah, bh[j2][t * 2], bh[j2][t * 2 + 1]);
                        mma16816(c[im][jn], ah, bl[j2][t * 2], bl[j2][t * 2 + 1]);
                        mma16816(c[im][jn], al, bh[j2][t * 2], bh[j2][t * 2 + 1]);
                    }
                }
            }
        }
        __syncthreads();
    }

    #pragma unroll
    for (int im = 0; im < 4; im++) {
        const int row = m0 + wm + im * 16 + (lane >> 2);
        #pragma unroll
        for (int jn = 0; jn < 4; jn++) {
            const int col = n0 + wn + jn * 8 + (lane & 3) * 2;
            float2 v0, v1;
            v0.x = c[im][jn][0];
            v0.y = c[im][jn][1];
            v1.x = c[im][jn][2];
            v1.y = c[im][jn][3];
            *(float2*)(C + (long long)row * ldc + col)       = v0;
            *(float2*)(C + (long long)(row + 8) * ldc + col) = v1;
        }
    }
}

// ---------------- split-K reduction: dst[b][i] = sum_s part[b*KS+s][i] -----
__global__ void reduce_k(const float* __restrict__ part, float* __restrict__ dst,
                         int KS, long long MN)
{
    const long long i = ((long long)blockIdx.x * 256 + threadIdx.x) * 4;
    const int b = blockIdx.y;
    const float* p = part + (long long)b * KS * MN + i;
    float4 acc = *(const float4*)p;
    for (int s = 1; s < KS; s++) {
        p += MN;
        const float4 v = *(const float4*)p;
        acc.x += v.x; acc.y += v.y; acc.z += v.z; acc.w += v.w;
    }
    *(float4*)(dst + (long long)b * MN + i) = acc;
}

// ---------------- fp32 split converter ----------------
__global__ void convert_split(const float* __restrict__ src,
                              ush* __restrict__ h, ush* __restrict__ l)
{
    const int i = blockIdx.x * blockDim.x + threadIdx.x;
    const float4 a = *(const float4*)(src + i * 8);
    const float4 b = *(const float4*)(src + i * 8 + 4);
    ush hh[8], ll[8];
    splitw(a.x, &hh[0], &ll[0]); splitw(a.y, &hh[1], &ll[1]);
    splitw(a.z, &hh[2], &ll[2]); splitw(a.w, &hh[3], &ll[3]);
    splitw(b.x, &hh[4], &ll[4]); splitw(b.y, &hh[5], &ll[5]);
    splitw(b.z, &hh[6], &ll[6]); splitw(b.w, &hh[7], &ll[7]);
    uint4 ph, pl;
    ph.x = (uin)hh[0] | ((uin)hh[1] << 16);
    ph.y = (uin)hh[2] | ((uin)hh[3] << 16);
    ph.z = (uin)hh[4] | ((uin)hh[5] << 16);
    ph.w = (uin)hh[6] | ((uin)hh[7] << 16);
    pl.x = (uin)ll[0] | ((uin)ll[1] << 16);
    pl.y = (uin)ll[2] | ((uin)ll[3] << 16);
    pl.z = (uin)ll[4] | ((uin)ll[5] << 16);
    pl.w = (uin)ll[6] | ((uin)ll[7] << 16);
    *(uint4*)(h + i * 8) = ph;
    *(uint4*)(l + i * 8) = pl;
}

// ---------------- w_kv_down padded split converter (576 -> 640 rows) -------
__global__ void convert_pad_kvd(const float* __restrict__ src,
                                ush* __restrict__ h, ush* __restrict__ l)
{
    const int i = blockIdx.x * blockDim.x + threadIdx.x;   // per 8 elements
    const long long base = (long long)i * 8;
    const int row = (int)(base >> 11);                      // /2048
    uint4 ph, pl;
    if (row < KCATv) {
        const float4 a = *(const float4*)(src + base);
        const float4 b = *(const float4*)(src + base + 4);
        ush hh[8], ll[8];
        splitw(a.x, &hh[0], &ll[0]); splitw(a.y, &hh[1], &ll[1]);
        splitw(a.z, &hh[2], &ll[2]); splitw(a.w, &hh[3], &ll[3]);
        splitw(b.x, &hh[4], &ll[4]); splitw(b.y, &hh[5], &ll[5]);
        splitw(b.z, &hh[6], &ll[6]); splitw(b.w, &hh[7], &ll[7]);
        ph.x = (uin)hh[0] | ((uin)hh[1] << 16);
        ph.y = (uin)hh[2] | ((uin)hh[3] << 16);
        ph.z = (uin)hh[4] | ((uin)hh[5] << 16);
        ph.w = (uin)hh[6] | ((uin)hh[7] << 16);
        pl.x = (uin)ll[0] | ((uin)ll[1] << 16);
        pl.y = (uin)ll[2] | ((uin)ll[3] << 16);
        pl.z = (uin)ll[4] | ((uin)ll[5] << 16);
        pl.w = (uin)ll[6] | ((uin)ll[7] << 16);
    } else {
        ph = make_uint4(0, 0, 0, 0);
        pl = make_uint4(0, 0, 0, 0);
    }
    *(uint4*)(h + base) = ph;
    *(uint4*)(l + base) = pl;
}

// ---------------- rmsnorm -> bf16 hi/lo ----------------
__global__ void rmsnorm_kernel(const float* __restrict__ xin,
                               const float* __restrict__ w,
                               ush* __restrict__ yh, ush* __restrict__ yl)
{
    const int r = blockIdx.x;
    const int tid = threadIdx.x;
    const float* xr = xin + r * Q_RANKv;
    float s = 0.f;
    #pragma unroll
    for (int i = 0; i < 3; i++) {
        const float v = xr[tid + i * 256];
        s += v * v;
    }
    __shared__ float red[256];
    red[tid] = s;
    __syncthreads();
    for (int o = 128; o > 0; o >>= 1) {
        if (tid < o) red[tid] += red[tid + o];
        __syncthreads();
    }
    const float inv = rsqrtf(red[0] / (float)Q_RANKv + EPSv);
    #pragma unroll
    for (int i = 0; i < 3; i++) {
        const int cc = tid + i * 256;
        const float v = xr[cc] * inv * w[cc];
        ush h, l;
        splitw(v, &h, &l);
        yh[r * Q_RANKv + cc] = h;
        yl[r * Q_RANKv + cc] = l;
    }
}

// ---------------- rope ----------------
__global__ void rope_kernel(float* __restrict__ q, float* __restrict__ kv,
                            const float* __restrict__ fc,
                            const float* __restrict__ fs)
{
    const int bl = blockIdx.x;
    const int l = bl & 31;
    const int tid = threadIdx.x;
    for (int wk = tid; wk < 544; wk += 256) {
        if (wk < 512) {
            const int h = wk >> 5;
            const int j = wk & 31;
            const float cc = fc[l * 32 + j];
            const float ss = fs[l * 32 + j];
            float* p = q + bl * (Hv * QKv) + h * QKv + D_NRv + 2 * j;
            const float xr = p[0], xi = p[1];
            p[0] = xr * cc - xi * ss;
            p[1] = xr * ss + xi * cc;
        } else {
            const int j = wk - 512;
            const float cc = fc[l * 32 + j];
            const float ss = fs[l * 32 + j];
            float* p = kv + bl * KVPADv + KV_RANKv + 2 * j;
            const float xr = p[0], xi = p[1];
            p[0] = xr * cc - xi * ss;
            p[1] = xr * ss + xi * cc;
        }
    }
}

// ---------------- build Acat -> bf16 hi/lo ----------------
__global__ void build_acat_kernel(const float* __restrict__ q,
                                  const float* __restrict__ w_kv_up,
                                  ush* __restrict__ Ah, ush* __restrict__ Al)
{
    const int bl = blockIdx.x;
    const int h  = blockIdx.y;
    const int b = bl >> 5, l = bl & 31;
    const int row = b * 512 + h * 32 + l;
    const int tid = threadIdx.x;

    __shared__ float qs[D_NRv];
    if (tid < D_NRv) qs[tid] = q[bl * (Hv * QKv) + h * QKv + tid];
    __syncthreads();

    const float* w = w_kv_up + (long long)(h * 256) * KV_RANKv;
    float a0 = 0.f, a1 = 0.f;
    #pragma unroll 4
    for (int d = 0; d < D_NRv; d++) {
        const float qd = qs[d];
        a0 += qd * w[d * KV_RANKv + tid];
        a1 += qd * w[d * KV_RANKv + tid + 256];
    }
    ush hh, ll;
    const long long base = (long long)row * KCATv;
    splitw(a0, &hh, &ll);
    Ah[base + tid] = hh;       Al[base + tid] = ll;
    splitw(a1, &hh, &ll);
    Ah[base + tid + 256] = hh; Al[base + tid + 256] = ll;
    if (tid < D_Rv) {
        const float v = q[bl * (Hv * QKv) + h * QKv + D_NRv + tid];
        splitw(v, &hh, &ll);
        Ah[base + KV_RANKv + tid] = hh;
        Al[base + KV_RANKv + tid] = ll;
    }
}

// ---------------- build Kcat -> bf16 hi/lo ----------------
__global__ void build_kcat_kernel(const float* __restrict__ kvc,
                                  const float* __restrict__ krc,
                                  const float* __restrict__ kvfresh,
                                  ush* __restrict__ Kh, ush* __restrict__ Kl)
{
    const int t = blockIdx.x;
    const int b = blockIdx.y;
    const int tid = threadIdx.x;
    const long long base = ((long long)b * MAXTv + t) * KCATv;
    if (t < STARTv) {
        const float* skv = kvc + ((long long)b * MAXTv + t) * KV_RANKv;
        const float* skr = krc + ((long long)b * MAXTv + t) * D_Rv;
        for (int cc = tid; cc < KCATv; cc += 256) {
            const float v = (cc < KV_RANKv) ? skv[cc] : skr[cc - KV_RANKv];
            ush h, l;
            splitw(v, &h, &l);
            Kh[base + cc] = h;
            Kl[base + cc] = l;
        }
    } else {
        const float* src = kvfresh + (b * Lv + (t - STARTv)) * KVPADv;
        for (int cc = tid; cc < KCATv; cc += 256) {
            ush h, l;
            splitw(src[cc], &h, &l);
            Kh[base + cc] = h;
            Kl[base + cc] = l;
        }
    }
}

// ---------------- transpose Kcat[:, :512] -> KcatT ----------------
__global__ void transpose_kcat(const ush* __restrict__ Kh, const ush* __restrict__ Kl,
                               ush* __restrict__ Th, ush* __restrict__ Tl)
{
    __shared__ ush th[32][33];
    __shared__ ush tl[32][33];
    const int b = blockIdx.z;
    const int t0 = blockIdx.x * 32;
    const int c0 = blockIdx.y * 32;
    const int tx = threadIdx.x;
    const int ty = threadIdx.y;
    #pragma unroll
    for (int i = 0; i < 32; i += 8) {
        const long long src = ((long long)b * MAXTv + t0 + ty + i) * KCATv + c0 + tx;
        th[ty + i][tx] = Kh[src];
        tl[ty + i][tx] = Kl[src];
    }
    __syncthreads();
    #pragma unroll
    for (int i = 0; i < 32; i += 8) {
        const long long dst = ((long long)b * 512 + c0 + ty + i) * MAXTv + t0 + tx;
        Th[dst] = th[tx][ty + i];
        Tl[dst] = tl[tx][ty + i];
    }
}

// ---------------- softmax -> P bf16 hi/lo ----------------
__global__ void softmax_kernel(const float* __restrict__ scores,
                               const float* __restrict__ mask,
                               ush* __restrict__ Ph, ush* __restrict__ Pl)
{
    const int id = blockIdx.x;
    const int l = id & 31;
    const int tid = threadIdx.x;
    const float* row = scores + (long long)id * MAXTv;
    const float* mrow = mask + l * MAXTv;
    const int base = tid * 16;

    float vals[16];
    float vmax = -3.4e38f;
    #pragma unroll
    for (int i = 0; i < 16; i += 4) {
        const float4 v4 = *(const float4*)(row + base + i);
        const float4 m4 = *(const float4*)(mrow + base + i);
        vals[i + 0] = v4.x * SCALEv + m4.x;
        vals[i + 1] = v4.y * SCALEv + m4.y;
        vals[i + 2] = v4.z * SCALEv + m4.z;
        vals[i + 3] = v4.w * SCALEv + m4.w;
        vmax = fmaxf(vmax, fmaxf(fmaxf(vals[i], vals[i + 1]),
                                 fmaxf(vals[i + 2], vals[i + 3])));
    }
    __shared__ float red[256];
    red[tid] = vmax;
    __syncthreads();
    for (int o = 128; o > 0; o >>= 1) {
        if (tid < o) red[tid] = fmaxf(red[tid], red[tid + o]);
        __syncthreads();
    }
    const float m = red[0];
    __syncthreads();

    float sum = 0.f;
    #pragma unroll
    for (int i = 0; i < 16; i++) {
        const float e = expf(vals[i] - m);
        vals[i] = e;
        sum += e;
    }
    red[tid] = sum;
    __syncthreads();
    for (int o = 128; o > 0; o >>= 1) {
        if (tid < o) red[tid] += red[tid + o];
        __syncthreads();
    }
    const float inv = 1.0f / red[0];

    uin wh[8], wl[8];
    #pragma unroll
    for (int i = 0; i < 8; i++) {
        ush h0, l0, h1, l1;
        splitw(vals[2 * i]     * inv, &h0, &l0);
        splitw(vals[2 * i + 1] * inv, &h1, &l1);
        wh[i] = (uin)h0 | ((uin)h1 << 16);
        wl[i] = (uin)l0 | ((uin)l1 << 16);
    }
    const long long off = (long long)id * MAXTv + base;
    *(uint4*)(Ph + off)     = make_uint4(wh[0], wh[1], wh[2], wh[3]);
    *(uint4*)(Ph + off + 8) = make_uint4(wh[4], wh[5], wh[6], wh[7]);
    *(uint4*)(Pl + off)     = make_uint4(wl[0], wl[1], wl[2], wl[3]);
    *(uint4*)(Pl + off + 8) = make_uint4(wl[4], wl[5], wl[6], wl[7]);
}

// ---------------- o_up -> o2 bf16 hi/lo ----------------
__global__ void o_up_kernel(const float* __restrict__ Oin,
                            const float* __restrict__ w_kv_up,
                            ush* __restrict__ o2h, ush* __restrict__ o2l)
{
    const int bl = blockIdx.x;
    const int h  = blockIdx.y;
    const int b = bl >> 5, l = bl & 31;
    const int tid = threadIdx.x;

    __shared__ float os[KV_RANKv];
    const float* orow = Oin + (long long)(b * 512 + h * 32 + l) * KV_RANKv;
    for (int cc = tid; cc < KV_RANKv; cc += 128)
        os[cc] = orow[cc];
    __syncthreads();

    const float* w = w_kv_up + (long long)(h * 256 + 128 + tid) * KV_RANKv;
    float acc = 0.f;
    #pragma unroll 4
    for (int k = 0; k < KV_RANKv; k += 4) {
        const float4 w4 = *(const float4*)(w + k);
        acc += os[k] * w4.x + os[k + 1] * w4.y + os[k + 2] * w4.z + os[k + 3] * w4.w;
    }
    ush hh, ll;
    splitw(acc, &hh, &ll);
    o2h[bl * (Hv * D_Vv) + h * D_Vv + tid] = hh;
    o2l[bl * (Hv * D_Vv) + h * D_Vv + tid] = ll;
}

// ---------------- launch ----------------------------------------------------
extern "C" void kernel_launch(void* const* d_in, const int* in_sizes, int n_in,
                              void* d_out, int out_size)
{
    const float* x         = (const float*)d_in[0];
    const float* freq_cos  = (const float*)d_in[2];
    const float* freq_sin  = (const float*)d_in[3];
    const float* mask      = (const float*)d_in[4];
    const float* kvc       = (const float*)d_in[5];
    const float* krc       = (const float*)d_in[6];
    const float* w_kv_down = (const float*)d_in[7];
    const float* w_q_down  = (const float*)d_in[8];
    const float* rms_q_w   = (const float*)d_in[9];
    const float* w_q_up    = (const float*)d_in[10];
    const float* w_kv_up   = (const float*)d_in[11];
    const float* w_out     = (const float*)d_in[12];
    float* out = (float*)d_out;

    cudaFuncSetAttribute(gemm_tc2, cudaFuncAttributeMaxDynamicSharedMemorySize,
                         SMEM_GT2);

    float* qlin = 0;  float* q = 0;  float* kvpad = 0;
    float* scores = 0; float* Obuf = 0; float* part = 0;
    ush *xh=0,*xl=0,*wqdh=0,*wqdl=0,*wkvh=0,*wkvl=0,*wquh=0,*wqul=0,*wouth=0,*woutl=0;
    ush *qdnh=0,*qdnl=0,*acath=0,*acatl=0,*kcath=0,*kcatl=0;
    ush *kTh=0,*kTl=0,*ph=0,*pl=0,*o2h=0,*o2l=0;

    cudaGetSymbolAddress((void**)&qlin,   g_qlin);
    cudaGetSymbolAddress((void**)&q,      g_q);
    cudaGetSymbolAddress((void**)&kvpad,  g_kvpad);
    cudaGetSymbolAddress((void**)&scores, g_scores);
    cudaGetSymbolAddress((void**)&Obuf,   g_O);
    cudaGetSymbolAddress((void**)&part,   g_part);
    cudaGetSymbolAddress((void**)&xh,     g_xh);
    cudaGetSymbolAddress((void**)&xl,     g_xl);
    cudaGetSymbolAddress((void**)&wqdh,   g_wqdh);
    cudaGetSymbolAddress((void**)&wqdl,   g_wqdl);
    cudaGetSymbolAddress((void**)&wkvh,   g_wkvh);
    cudaGetSymbolAddress((void**)&wkvl,   g_wkvl);
    cudaGetSymbolAddress((void**)&wquh,   g_wquh);
    cudaGetSymbolAddress((void**)&wqul,   g_wqul);
    cudaGetSymbolAddress((void**)&wouth,  g_wouth);
    cudaGetSymbolAddress((void**)&woutl,  g_woutl);
    cudaGetSymbolAddress((void**)&qdnh,   g_qdnh);
    cudaGetSymbolAddress((void**)&qdnl,   g_qdnl);
    cudaGetSymbolAddress((void**)&acath,  g_acath);
    cudaGetSymbolAddress((void**)&acatl,  g_acatl);
    cudaGetSymbolAddress((void**)&kcath,  g_kcath);
    cudaGetSymbolAddress((void**)&kcatl,  g_kcatl);
    cudaGetSymbolAddress((void**)&kTh,    g_kTh);
    cudaGetSymbolAddress((void**)&kTl,    g_kTl);
    cudaGetSymbolAddress((void**)&ph,     g_ph);
    cudaGetSymbolAddress((void**)&pl,     g_pl);
    cudaGetSymbolAddress((void**)&o2h,    g_o2h);
    cudaGetSymbolAddress((void**)&o2l,    g_o2l);

    // 0) pre-split inputs/weights
    convert_split<<<(BLv * DIMv) / 8 / 256, 256>>>(x, xh, xl);
    convert_split<<<(Q_RANKv * DIMv) / 8 / 256, 256>>>(w_q_down, wqdh, wqdl);
    convert_split<<<(Hv * QKv * Q_RANKv) / 8 / 256, 256>>>(w_q_up, wquh, wqul);
    convert_split<<<(DIMv * DIMv) / 8 / 256, 256>>>(w_out, wouth, woutl);
    convert_pad_kvd<<<(KVPADv * DIMv) / 8 / 256, 256>>>(w_kv_down, wkvh, wkvl);

    // 1) q_down: (256,768,K=2048), split-K 8
    gemm_tc2<<<dim3(Q_RANKv / 128, BLv / 128, 8), 256, SMEM_GT2>>>(
        xh, xl, wqdh, wqdl, part, BLv, Q_RANKv, DIMv, DIMv, Q_RANKv,
        0, 0, (long long)BLv * Q_RANKv, 8, 256);
    reduce_k<<<dim3(BLv * Q_RANKv / 4 / 256, 1), 256>>>(
        part, qlin, 8, (long long)BLv * Q_RANKv);

    // 2) kv_down (padded N=640): split-K 8
    gemm_tc2<<<dim3(KVPADv / 128, BLv / 128, 8), 256, SMEM_GT2>>>(
        xh, xl, wkvh, wkvl, part, BLv, KVPADv, DIMv, DIMv, KVPADv,
        0, 0, (long long)BLv * KVPADv, 8, 256);
    reduce_k<<<dim3(BLv * KVPADv / 4 / 256, 1), 256>>>(
        part, kvpad, 8, (long long)BLv * KVPADv);

    // 3) rmsnorm -> qdn hi/lo
    rmsnorm_kernel<<<BLv, 256>>>(qlin, rms_q_w, qdnh, qdnl);

    // 4) q_up: (256,3072,768), split-K 4
    gemm_tc2<<<dim3((Hv * QKv) / 128, BLv / 128, 4), 256, SMEM_GT2>>>(
        qdnh, qdnl, wquh, wqul, part, BLv, Hv * QKv, Q_RANKv, Q_RANKv, Hv * QKv,
        0, 0, (long long)BLv * Hv * QKv, 4, 192);
    reduce_k<<<dim3(BLv * Hv * QKv / 4 / 256, 1), 256>>>(
        part, q, 4, (long long)BLv * Hv * QKv);

    // 5) rope (q + fresh k_rope in kvpad)
    rope_kernel<<<BLv, 256>>>(q, kvpad, freq_cos, freq_sin);

    // 6) Acat hi/lo
    build_acat_kernel<<<dim3(BLv, Hv), 256>>>(q, w_kv_up, acath, acatl);

    // 7) Kcat hi/lo (+ transpose for PV)
    build_kcat_kernel<<<dim3(MAXTv, Bv), 256>>>(kvc, krc, kvpad, kcath, kcatl);
    transpose_kcat<<<dim3(MAXTv / 32, 512 / 32, Bv), dim3(32, 8)>>>(
        kcath, kcatl, kTh, kTl);

    // 8) scores: batched (512,4096,576), KS=1 direct
    gemm_tc2<<<dim3(MAXTv / 128, 512 / 128, Bv), 256, SMEM_GT2>>>(
        acath, acatl, kcath, kcatl, scores, 512, MAXTv, KCATv, KCATv, MAXTv,
        (long long)512 * KCATv, (long long)MAXTv * KCATv, (long long)512 * MAXTv,
        1, KCATv);

    // 9) softmax -> P hi/lo
    softmax_kernel<<<Bv * 512, 256>>>(scores, mask, ph, pl);

    // 10) O = P @ KcatT^T: batched (512,512,4096), split-K 4
    gemm_tc2<<<dim3(KV_RANKv / 128, 512 / 128, Bv * 4), 256, SMEM_GT2>>>(
        ph, pl, kTh, kTl, part, 512, KV_RANKv, MAXTv, MAXTv, KV_RANKv,
        (long long)512 * MAXTv, (long long)512 * MAXTv, (long long)512 * KV_RANKv,
        4, 1024);
    reduce_k<<<dim3(512 * KV_RANKv / 4 / 256, Bv), 256>>>(
        part, Obuf, 4, (long long)512 * KV_RANKv);

    // 11) o2 hi/lo
    o_up_kernel<<<dim3(BLv, Hv), 128>>>(Obuf, w_kv_up, o2h, o2l);

    // 12) out: (256,2048,2048), split-K 4
    gemm_tc2<<<dim3(DIMv / 128, BLv / 128, 4), 256, SMEM_GT2>>>(
        o2h, o2l, wouth, woutl, part, BLv, DIMv, DIMv, DIMv, DIMv,
        0, 0, (long long)BLv * DIMv, 4, 512);
    reduce_k<<<dim3(BLv * DIMv / 4 / 256, 1), 256>>>(
        part, out, 4, (long long)BLv * DIMv);
}

// round 7
// speedup vs baseline: 3.1522x; 1.5371x over previous
#include <cuda_runtime.h>
#include <math.h>
#include <stdint.h>

typedef unsigned short ush;
typedef unsigned int   uin;

// ---------------- problem constants ----------------
#define Bv      8
#define Lv      32
#define BLv     256
#define DIMv    2048
#define KV_RANKv 512
#define Q_RANKv 768
#define Hv      16
#define D_NRv   128
#define D_Rv    64
#define D_Vv    128
#define QKv     192
#define MAXTv   4096
#define STARTv  4064
#define KCATv   576
#define KVPADv  640
#define EPSv    1.1920929e-07f
#define SCALEv  0.07216878364870323f

// ---------------- scratch (device globals) ----------------
__device__ float g_qlin  [BLv * Q_RANKv];
__device__ float g_q     [BLv * Hv * QKv];      // q fp32; later reused as o2f
__device__ float g_kvpad [BLv * KVPADv];
__device__ float g_scores[(long long)Bv * 512 * MAXTv];
__device__ float g_O     [Bv * 512 * 512];      // O2 reordered [h*256+b*32+l][512]
__device__ float g_part  [Bv * 4 * 512 * 512];  // split-K partials / acat scratch

__device__ ush g_xh   [BLv * DIMv],        g_xl   [BLv * DIMv];
__device__ ush g_wqdh [Q_RANKv * DIMv],    g_wqdl [Q_RANKv * DIMv];
__device__ ush g_wkvh [KVPADv * DIMv],     g_wkvl [KVPADv * DIMv];
__device__ ush g_wquh [Hv*QKv * Q_RANKv],  g_wqul [Hv*QKv * Q_RANKv];
__device__ ush g_wouth[DIMv * DIMv],       g_woutl[DIMv * DIMv];
__device__ ush g_wvuh [Hv * 256 * 512],    g_wvul [Hv * 256 * 512];
__device__ ush g_qdnh [BLv * Q_RANKv],     g_qdnl [BLv * Q_RANKv];
__device__ ush g_qsh  [BLv * Hv * QKv],    g_qsl  [BLv * Hv * QKv];
__device__ ush g_acath[Bv*512 * KCATv],    g_acatl[Bv*512 * KCATv];
__device__ ush g_kcath[(long long)Bv*MAXTv*KCATv], g_kcatl[(long long)Bv*MAXTv*KCATv];
__device__ ush g_o2sh [Bv * 512 * 512],    g_o2sl [Bv * 512 * 512];
__device__ ush g_ph   [(long long)Bv*512*MAXTv],   g_pl   [(long long)Bv*512*MAXTv];
__device__ ush g_o2h  [BLv * Hv*D_Vv],     g_o2l  [BLv * Hv*D_Vv];

// ---------------- bf16 bit helpers ----------------
__device__ __forceinline__ ush bf16_rn(float x) {
    uin u = __float_as_uint(x);
    uin r = u + 0x7FFFu + ((u >> 16) & 1u);
    return (ush)(r >> 16);
}
__device__ __forceinline__ float bf16_tof(ush h) {
    return __uint_as_float(((uin)h) << 16);
}
__device__ __forceinline__ void splitw(float x, ush* h, ush* l) {
    ush hh = bf16_rn(x);
    *h = hh;
    *l = bf16_rn(x - bf16_tof(hh));
}

__device__ __forceinline__ void ldmx4(uin* r, const void* p) {
    uin a = (uin)__cvta_generic_to_shared(p);
    asm volatile("ldmatrix.sync.aligned.m8n8.x4.shared.b16 {%0,%1,%2,%3}, [%4];"
                 : "=r"(r[0]), "=r"(r[1]), "=r"(r[2]), "=r"(r[3]) : "r"(a));
}
__device__ __forceinline__ void ldmx4t(uin* r, const void* p) {
    uin a = (uin)__cvta_generic_to_shared(p);
    asm volatile("ldmatrix.sync.aligned.m8n8.x4.trans.shared.b16 {%0,%1,%2,%3}, [%4];"
                 : "=r"(r[0]), "=r"(r[1]), "=r"(r[2]), "=r"(r[3]) : "r"(a));
}
__device__ __forceinline__ void mma16816(float* c, const uin* a, uin b0, uin b1) {
    asm volatile(
        "mma.sync.aligned.m16n8k16.row.col.f32.bf16.bf16.f32 "
        "{%0,%1,%2,%3},{%4,%5,%6,%7},{%8,%9},{%0,%1,%2,%3};\n"
        : "+f"(c[0]), "+f"(c[1]), "+f"(c[2]), "+f"(c[3])
        : "r"(a[0]), "r"(a[1]), "r"(a[2]), "r"(a[3]), "r"(b0), "r"(b1));
}
__device__ __forceinline__ void cpa16(void* s, const void* g) {
    uin sa = (uin)__cvta_generic_to_shared(s);
    asm volatile("cp.async.cg.shared.global [%0], [%1], 16;" :: "r"(sa), "l"(g));
}

// ====================================================================
//  bf16 hi/lo tensor-core GEMM, cp.async double-buffered, split-K.
//  BT=true : B is [N,K] row-major.  BT=false: B is [K,N] row-major
//  (staged [k][n], consumed via ldmatrix.trans).
//  blockIdx.z = batch * KS + kslice; slice covers KL of K.
// ====================================================================
#define ATILE 5120                 // 128 rows x 40 ush
#define SMEM_GT2 81920

template <bool BT>
__device__ __forceinline__ void stage_ld(ush* sm,
        const ush* Ahg, const ush* Alg, const ush* Bhg, const ush* Blg,
        int m0, int n0, int k0, int lda, int ldb, int tid)
{
    constexpr int BTILE = BT ? 5120 : 4352;
    {
        const int row = tid >> 1;
        const int c2  = (tid & 1) * 2;
        #pragma unroll
        for (int j = 0; j < 2; j++) {
            const int col = (c2 + j) * 8;
            const long long off = (long long)(m0 + row) * lda + k0 + col;
            ush* d = sm + row * 40 + col;
            cpa16(d,         Ahg + off);
            cpa16(d + ATILE, Alg + off);
        }
    }
    if (BT) {
        const int row = tid >> 1;
        const int c2  = (tid & 1) * 2;
        #pragma unroll
        for (int j = 0; j < 2; j++) {
            const int col = (c2 + j) * 8;
            const long long off = (long long)(n0 + row) * ldb + k0 + col;
            ush* d = sm + 2 * ATILE + row * 40 + col;
            cpa16(d,         Bhg + off);
            cpa16(d + BTILE, Blg + off);
        }
    } else {
        const int kr = tid >> 3;          // 0..31
        const int cp = (tid & 7) * 2;
        #pragma unroll
        for (int j = 0; j < 2; j++) {
            const int nof = (cp + j) * 8;
            const long long off = (long long)(k0 + kr) * ldb + n0 + nof;
            ush* d = sm + 2 * ATILE + kr * 136 + nof;
            cpa16(d,         Bhg + off);
            cpa16(d + BTILE, Blg + off);
        }
    }
}

template <bool BT>
__global__ __launch_bounds__(256, 2)
void gemm_tc2(const ush* __restrict__ Ahg, const ush* __restrict__ Alg,
              const ush* __restrict__ Bhg, const ush* __restrict__ Blg,
              float* __restrict__ C,
              int M, int N, int lda, int ldb, int ldc,
              long long sA, long long sB, long long sC,
              int KS, int KL)
{
    extern __shared__ ush dsm[];
    constexpr int BTILE = BT ? 5120 : 4352;
    constexpr int STAGE = 2 * ATILE + 2 * BTILE;

    const int bz = blockIdx.z;
    const int batch = bz / KS;
    const int ks    = bz - batch * KS;
    Ahg += batch * sA + (long long)ks * KL;
    Alg += batch * sA + (long long)ks * KL;
    if (BT) {
        Bhg += batch * sB + (long long)ks * KL;
        Blg += batch * sB + (long long)ks * KL;
    } else {
        Bhg += batch * sB + (long long)ks * KL * ldb;
        Blg += batch * sB + (long long)ks * KL * ldb;
    }
    C += (long long)bz * sC;

    const int m0 = blockIdx.y * 128;
    const int n0 = blockIdx.x * 128;
    const int tid  = threadIdx.x;
    const int wid  = tid >> 5;
    const int lane = tid & 31;
    const int wm = (wid & 1) * 64;
    const int wn = (wid >> 1) * 32;
    const int lr = lane & 7;
    const int lg = lane >> 3;

    float c[4][4][4];
    #pragma unroll
    for (int i = 0; i < 4; i++)
        #pragma unroll
        for (int j = 0; j < 4; j++)
            #pragma unroll
            for (int t = 0; t < 4; t++)
                c[i][j][t] = 0.0f;

    const int KT = KL >> 5;

    stage_ld<BT>(dsm, Ahg, Alg, Bhg, Blg, m0, n0, 0, lda, ldb, tid);
    asm volatile("cp.async.commit_group;");

    for (int kt = 0; kt < KT; kt++) {
        const ush* cur = dsm + (kt & 1) * STAGE;
        if (kt + 1 < KT) {
            stage_ld<BT>(dsm + ((kt + 1) & 1) * STAGE,
                         Ahg, Alg, Bhg, Blg, m0, n0, (kt + 1) << 5, lda, ldb, tid);
            asm volatile("cp.async.commit_group;");
            asm volatile("cp.async.wait_group 1;");
        } else {
            asm volatile("cp.async.wait_group 0;");
        }
        __syncthreads();

        const ush* sAh = cur;
        const ush* sAl = cur + ATILE;
        const ush* sBh = cur + 2 * ATILE;
        const ush* sBl = cur + 2 * ATILE + BTILE;

        #pragma unroll
        for (int kk = 0; kk < 32; kk += 16) {
            uin bh[2][4], bl[2][4];
            #pragma unroll
            for (int j2 = 0; j2 < 2; j2++) {
                if (BT) {
                    const int nrow = wn + j2 * 16 + lr + ((lg & 2) << 2);
                    const int kcol = kk + ((lg & 1) << 3);
                    ldmx4(bh[j2], sBh + nrow * 40 + kcol);
                    ldmx4(bl[j2], sBl + nrow * 40 + kcol);
                } else {
                    const int krow = kk + lr + ((lg & 1) << 3);
                    const int ncol = wn + j2 * 16 + ((lg & 2) << 2);
                    ldmx4t(bh[j2], sBh + krow * 136 + ncol);
                    ldmx4t(bl[j2], sBl + krow * 136 + ncol);
                }
            }
            #pragma unroll
            for (int im = 0; im < 4; im++) {
                uin ah[4], al[4];
                const int mrow = wm + im * 16 + lr + ((lg & 1) << 3);
                const int kcol = kk + ((lg & 2) << 2);
                ldmx4(ah, sAh + mrow * 40 + kcol);
                ldmx4(al, sAl + mrow * 40 + kcol);
                #pragma unroll
                for (int j2 = 0; j2 < 2; j2++) {
                    #pragma unroll
                    for (int t = 0; t < 2; t++) {
                        const int jn = j2 * 2 + t;
                        mma16816(c[im][jn], ah, bh[j2][t * 2], bh[j2][t * 2 + 1]);
                        mma16816(c[im][jn], ah, bl[j2][t * 2], bl[j2][t * 2 + 1]);
                        mma16816(c[im][jn], al, bh[j2][t * 2], bh[j2][t * 2 + 1]);
                    }
                }
            }
        }
        __syncthreads();
    }

    #pragma unroll
    for (int im = 0; im < 4; im++) {
        const int row = m0 + wm + im * 16 + (lane >> 2);
        #pragma unroll
        for (int jn = 0; jn < 4; jn++) {
            const int col = n0 + wn + jn * 8 + (lane & 3) * 2;
            float2 v0, v1;
            v0.x = c[im][jn][0];
            v0.y = c[im][jn][1];
            v1.x = c[im][jn][2];
            v1.y = c[im][jn][3];
            *(float2*)(C + (long long)row * ldc + col)       = v0;
            *(float2*)(C + (long long)(row + 8) * ldc + col) = v1;
        }
    }
}

// ---------------- split-K reduction ----------------
__global__ void reduce_k(const float* __restrict__ part, float* __restrict__ dst,
                         int KS, long long MN)
{
    const long long i = ((long long)blockIdx.x * 256 + threadIdx.x) * 4;
    const int b = blockIdx.y;
    const float* p = part + (long long)b * KS * MN + i;
    float4 acc = *(const float4*)p;
    for (int s = 1; s < KS; s++) {
        p += MN;
        const float4 v = *(const float4*)p;
        acc.x += v.x; acc.y += v.y; acc.z += v.z; acc.w += v.w;
    }
    *(float4*)(dst + (long long)b * MN + i) = acc;
}

// ---------------- PV reduction with per-head reorder ----------------
__global__ void reduce_pv(const float* __restrict__ part, float* __restrict__ O2)
{
    const long long i = ((long long)blockIdx.x * 256 + threadIdx.x) * 4;
    const int b = blockIdx.y;
    const float* p = part + (long long)b * 4 * 262144 + i;
    float4 acc = *(const float4*)p;
    #pragma unroll
    for (int s = 1; s < 4; s++) {
        const float4 v = *(const float4*)(p + (long long)s * 262144);
        acc.x += v.x; acc.y += v.y; acc.z += v.z; acc.w += v.w;
    }
    const int r = (int)(i >> 9);
    const int cc = (int)(i & 511);
    *(float4*)(O2 + ((long long)((r >> 5) * 256 + b * 32 + (r & 31)) * 512 + cc)) = acc;
}

// ---------------- fp32 split converter ----------------
__global__ void convert_split(const float* __restrict__ src,
                              ush* __restrict__ h, ush* __restrict__ l)
{
    const int i = blockIdx.x * blockDim.x + threadIdx.x;
    const float4 a = *(const float4*)(src + i * 8);
    const float4 b = *(const float4*)(src + i * 8 + 4);
    ush hh[8], ll[8];
    splitw(a.x, &hh[0], &ll[0]); splitw(a.y, &hh[1], &ll[1]);
    splitw(a.z, &hh[2], &ll[2]); splitw(a.w, &hh[3], &ll[3]);
    splitw(b.x, &hh[4], &ll[4]); splitw(b.y, &hh[5], &ll[5]);
    splitw(b.z, &hh[6], &ll[6]); splitw(b.w, &hh[7], &ll[7]);
    uint4 ph, pl;
    ph.x = (uin)hh[0] | ((uin)hh[1] << 16);
    ph.y = (uin)hh[2] | ((uin)hh[3] << 16);
    ph.z = (uin)hh[4] | ((uin)hh[5] << 16);
    ph.w = (uin)hh[6] | ((uin)hh[7] << 16);
    pl.x = (uin)ll[0] | ((uin)ll[1] << 16);
    pl.y = (uin)ll[2] | ((uin)ll[3] << 16);
    pl.z = (uin)ll[4] | ((uin)ll[5] << 16);
    pl.w = (uin)ll[6] | ((uin)ll[7] << 16);
    *(uint4*)(h + i * 8) = ph;
    *(uint4*)(l + i * 8) = pl;
}

// ---------------- w_kv_down padded split converter (576 -> 640 rows) -------
__global__ void convert_pad_kvd(const float* __restrict__ src,
                                ush* __restrict__ h, ush* __restrict__ l)
{
    const int i = blockIdx.x * blockDim.x + threadIdx.x;
    const long long base = (long long)i * 8;
    const int row = (int)(base >> 11);
    uint4 ph, pl;
    if (row < KCATv) {
        const float4 a = *(const float4*)(src + base);
        const float4 b = *(const float4*)(src + base + 4);
        ush hh[8], ll[8];
        splitw(a.x, &hh[0], &ll[0]); splitw(a.y, &hh[1], &ll[1]);
        splitw(a.z, &hh[2], &ll[2]); splitw(a.w, &hh[3], &ll[3]);
        splitw(b.x, &hh[4], &ll[4]); splitw(b.y, &hh[5], &ll[5]);
        splitw(b.z, &hh[6], &ll[6]); splitw(b.w, &hh[7], &ll[7]);
        ph.x = (uin)hh[0] | ((uin)hh[1] << 16);
        ph.y = (uin)hh[2] | ((uin)hh[3] << 16);
        ph.z = (uin)hh[4] | ((uin)hh[5] << 16);
        ph.w = (uin)hh[6] | ((uin)hh[7] << 16);
        pl.x = (uin)ll[0] | ((uin)ll[1] << 16);
        pl.y = (uin)ll[2] | ((uin)ll[3] << 16);
        pl.z = (uin)ll[4] | ((uin)ll[5] << 16);
        pl.w = (uin)ll[6] | ((uin)ll[7] << 16);
    } else {
        ph = make_uint4(0, 0, 0, 0);
        pl = make_uint4(0, 0, 0, 0);
    }
    *(uint4*)(h + base) = ph;
    *(uint4*)(l + base) = pl;
}

// ---------------- rmsnorm -> bf16 hi/lo ----------------
__global__ void rmsnorm_kernel(const float* __restrict__ xin,
                               const float* __restrict__ w,
                               ush* __restrict__ yh, ush* __restrict__ yl)
{
    const int r = blockIdx.x;
    const int tid = threadIdx.x;
    const float* xr = xin + r * Q_RANKv;
    float s = 0.f;
    #pragma unroll
    for (int i = 0; i < 3; i++) {
        const float v = xr[tid + i * 256];
        s += v * v;
    }
    __shared__ float red[256];
    red[tid] = s;
    __syncthreads();
    for (int o = 128; o > 0; o >>= 1) {
        if (tid < o) red[tid] += red[tid + o];
        __syncthreads();
    }
    const float inv = rsqrtf(red[0] / (float)Q_RANKv + EPSv);
    #pragma unroll
    for (int i = 0; i < 3; i++) {
        const int cc = tid + i * 256;
        const float v = xr[cc] * inv * w[cc];
        ush h, l;
        splitw(v, &h, &l);
        yh[r * Q_RANKv + cc] = h;
        yl[r * Q_RANKv + cc] = l;
    }
}

// ---------------- rope ----------------
__global__ void rope_kernel(float* __restrict__ q, float* __restrict__ kv,
                            const float* __restrict__ fc,
                            const float* __restrict__ fs)
{
    const int bl = blockIdx.x;
    const int l = bl & 31;
    const int tid = threadIdx.x;
    for (int wk = tid; wk < 544; wk += 256) {
        if (wk < 512) {
            const int h = wk >> 5;
            const int j = wk & 31;
            const float cc = fc[l * 32 + j];
            const float ss = fs[l * 32 + j];
            float* p = q + bl * (Hv * QKv) + h * QKv + D_NRv + 2 * j;
            const float xr = p[0], xi = p[1];
            p[0] = xr * cc - xi * ss;
            p[1] = xr * ss + xi * cc;
        } else {
            const int j = wk - 512;
            const float cc = fc[l * 32 + j];
            const float ss = fs[l * 32 + j];
            float* p = kv + bl * KVPADv + KV_RANKv + 2 * j;
            const float xr = p[0], xi = p[1];
            p[0] = xr * cc - xi * ss;
            p[1] = xr * ss + xi * cc;
        }
    }
}

// ---------------- assemble Acat from GEMM scratch + rope cols ----------------
__global__ void assemble_acat(const float* __restrict__ scr,
                              const ush* __restrict__ qh, const ush* __restrict__ ql,
                              ush* __restrict__ Ah, ush* __restrict__ Al)
{
    const int row = blockIdx.x;           // 0..4095 = b*512 + h*32 + l
    const int b = row >> 9;
    const int r = row & 511;
    const int h = r >> 5;
    const int l = r & 31;
    const int tid = threadIdx.x;          // 256
    const long long dbase = (long long)row * KCATv;
    const float* s = scr + ((long long)h * 256 + b * 32 + l) * 512;
    #pragma unroll
    for (int i = 0; i < 2; i++) {
        const int cc = tid + i * 256;
        ush hh, ll;
        splitw(s[cc], &hh, &ll);
        Ah[dbase + cc] = hh;
        Al[dbase + cc] = ll;
    }
    if (tid < D_Rv) {
        const long long qi = (long long)(b * 32 + l) * (Hv * QKv) + h * QKv + D_NRv + tid;
        Ah[dbase + KV_RANKv + tid] = qh[qi];
        Al[dbase + KV_RANKv + tid] = ql[qi];
    }
}

// ---------------- build Kcat -> bf16 hi/lo ----------------
__global__ void build_kcat_kernel(const float* __restrict__ kvc,
                                  const float* __restrict__ krc,
                                  const float* __restrict__ kvfresh,
                                  ush* __restrict__ Kh, ush* __restrict__ Kl)
{
    const int t = blockIdx.x;
    const int b = blockIdx.y;
    const int tid = threadIdx.x;
    const long long base = ((long long)b * MAXTv + t) * KCATv;
    if (t < STARTv) {
        const float* skv = kvc + ((long long)b * MAXTv + t) * KV_RANKv;
        const float* skr = krc + ((long long)b * MAXTv + t) * D_Rv;
        for (int cc = tid; cc < KCATv; cc += 256) {
            const float v = (cc < KV_RANKv) ? skv[cc] : skr[cc - KV_RANKv];
            ush h, l;
            splitw(v, &h, &l);
            Kh[base + cc] = h;
            Kl[base + cc] = l;
        }
    } else {
        const float* src = kvfresh + (b * Lv + (t - STARTv)) * KVPADv;
        for (int cc = tid; cc < KCATv; cc += 256) {
            ush h, l;
            splitw(src[cc], &h, &l);
            Kh[base + cc] = h;
            Kl[base + cc] = l;
        }
    }
}

// ---------------- softmax -> P bf16 hi/lo ----------------
__global__ void softmax_kernel(const float* __restrict__ scores,
                               const float* __restrict__ mask,
                               ush* __restrict__ Ph, ush* __restrict__ Pl)
{
    const int id = blockIdx.x;
    const int l = id & 31;
    const int tid = threadIdx.x;
    const float* row = scores + (long long)id * MAXTv;
    const float* mrow = mask + l * MAXTv;
    const int base = tid * 16;

    float vals[16];
    float vmax = -3.4e38f;
    #pragma unroll
    for (int i = 0; i < 16; i += 4) {
        const float4 v4 = *(const float4*)(row + base + i);
        const float4 m4 = *(const float4*)(mrow + base + i);
        vals[i + 0] = v4.x * SCALEv + m4.x;
        vals[i + 1] = v4.y * SCALEv + m4.y;
        vals[i + 2] = v4.z * SCALEv + m4.z;
        vals[i + 3] = v4.w * SCALEv + m4.w;
        vmax = fmaxf(vmax, fmaxf(fmaxf(vals[i], vals[i + 1]),
                                 fmaxf(vals[i + 2], vals[i + 3])));
    }
    __shared__ float red[256];
    red[tid] = vmax;
    __syncthreads();
    for (int o = 128; o > 0; o >>= 1) {
        if (tid < o) red[tid] = fmaxf(red[tid], red[tid + o]);
        __syncthreads();
    }
    const float m = red[0];
    __syncthreads();

    float sum = 0.f;
    #pragma unroll
    for (int i = 0; i < 16; i++) {
        const float e = expf(vals[i] - m);
        vals[i] = e;
        sum += e;
    }
    red[tid] = sum;
    __syncthreads();
    for (int o = 128; o > 0; o >>= 1) {
        if (tid < o) red[tid] += red[tid + o];
        __syncthreads();
    }
    const float inv = 1.0f / red[0];

    uin wh[8], wl[8];
    #pragma unroll
    for (int i = 0; i < 8; i++) {
        ush h0, l0, h1, l1;
        splitw(vals[2 * i]     * inv, &h0, &l0);
        splitw(vals[2 * i + 1] * inv, &h1, &l1);
        wh[i] = (uin)h0 | ((uin)h1 << 16);
        wl[i] = (uin)l0 | ((uin)l1 << 16);
    }
    const long long off = (long long)id * MAXTv + base;
    *(uint4*)(Ph + off)     = make_uint4(wh[0], wh[1], wh[2], wh[3]);
    *(uint4*)(Ph + off + 8) = make_uint4(wh[4], wh[5], wh[6], wh[7]);
    *(uint4*)(Pl + off)     = make_uint4(wl[0], wl[1], wl[2], wl[3]);
    *(uint4*)(Pl + off + 8) = make_uint4(wl[4], wl[5], wl[6], wl[7]);
}

// ---------------- launch ----------------------------------------------------
extern "C" void kernel_launch(void* const* d_in, const int* in_sizes, int n_in,
                              void* d_out, int out_size)
{
    const float* x         = (const float*)d_in[0];
    const float* freq_cos  = (const float*)d_in[2];
    const float* freq_sin  = (const float*)d_in[3];
    const float* mask      = (const float*)d_in[4];
    const float* kvc       = (const float*)d_in[5];
    const float* krc       = (const float*)d_in[6];
    const float* w_kv_down = (const float*)d_in[7];
    const float* w_q_down  = (const float*)d_in[8];
    const float* rms_q_w   = (const float*)d_in[9];
    const float* w_q_up    = (const float*)d_in[10];
    const float* w_kv_up   = (const float*)d_in[11];
    const float* w_out     = (const float*)d_in[12];
    float* out = (float*)d_out;

    cudaFuncSetAttribute(gemm_tc2<true>,
                         cudaFuncAttributeMaxDynamicSharedMemorySize, SMEM_GT2);
    cudaFuncSetAttribute(gemm_tc2<false>,
                         cudaFuncAttributeMaxDynamicSharedMemorySize, SMEM_GT2);

    float *qlin=0, *q=0, *kvpad=0, *scores=0, *O2=0, *part=0;
    ush *xh=0,*xl=0,*wqdh=0,*wqdl=0,*wkvh=0,*wkvl=0,*wquh=0,*wqul=0;
    ush *wouth=0,*woutl=0,*wvuh=0,*wvul=0;
    ush *qdnh=0,*qdnl=0,*qsh=0,*qsl=0,*acath=0,*acatl=0,*kcath=0,*kcatl=0;
    ush *o2sh=0,*o2sl=0,*ph=0,*pl=0,*o2h=0,*o2l=0;

    cudaGetSymbolAddress((void**)&qlin,   g_qlin);
    cudaGetSymbolAddress((void**)&q,      g_q);
    cudaGetSymbolAddress((void**)&kvpad,  g_kvpad);
    cudaGetSymbolAddress((void**)&scores, g_scores);
    cudaGetSymbolAddress((void**)&O2,     g_O);
    cudaGetSymbolAddress((void**)&part,   g_part);
    cudaGetSymbolAddress((void**)&xh,     g_xh);
    cudaGetSymbolAddress((void**)&xl,     g_xl);
    cudaGetSymbolAddress((void**)&wqdh,   g_wqdh);
    cudaGetSymbolAddress((void**)&wqdl,   g_wqdl);
    cudaGetSymbolAddress((void**)&wkvh,   g_wkvh);
    cudaGetSymbolAddress((void**)&wkvl,   g_wkvl);
    cudaGetSymbolAddress((void**)&wquh,   g_wquh);
    cudaGetSymbolAddress((void**)&wqul,   g_wqul);
    cudaGetSymbolAddress((void**)&wouth,  g_wouth);
    cudaGetSymbolAddress((void**)&woutl,  g_woutl);
    cudaGetSymbolAddress((void**)&wvuh,   g_wvuh);
    cudaGetSymbolAddress((void**)&wvul,   g_wvul);
    cudaGetSymbolAddress((void**)&qdnh,   g_qdnh);
    cudaGetSymbolAddress((void**)&qdnl,   g_qdnl);
    cudaGetSymbolAddress((void**)&qsh,    g_qsh);
    cudaGetSymbolAddress((void**)&qsl,    g_qsl);
    cudaGetSymbolAddress((void**)&acath,  g_acath);
    cudaGetSymbolAddress((void**)&acatl,  g_acatl);
    cudaGetSymbolAddress((void**)&kcath,  g_kcath);
    cudaGetSymbolAddress((void**)&kcatl,  g_kcatl);
    cudaGetSymbolAddress((void**)&o2sh,   g_o2sh);
    cudaGetSymbolAddress((void**)&o2sl,   g_o2sl);
    cudaGetSymbolAddress((void**)&ph,     g_ph);
    cudaGetSymbolAddress((void**)&pl,     g_pl);
    cudaGetSymbolAddress((void**)&o2h,    g_o2h);
    cudaGetSymbolAddress((void**)&o2l,    g_o2l);

    // 0) pre-split inputs/weights
    convert_split<<<(BLv * DIMv) / 2048, 256>>>(x, xh, xl);
    convert_split<<<(Q_RANKv * DIMv) / 2048, 256>>>(w_q_down, wqdh, wqdl);
    convert_split<<<(Hv * QKv * Q_RANKv) / 2048, 256>>>(w_q_up, wquh, wqul);
    convert_split<<<(DIMv * DIMv) / 2048, 256>>>(w_out, wouth, woutl);
    convert_split<<<(Hv * 256 * 512) / 2048, 256>>>(w_kv_up, wvuh, wvul);
    convert_pad_kvd<<<(KVPADv * DIMv) / 2048, 256>>>(w_kv_down, wkvh, wkvl);

    // 1) q_down (256,768,K=2048), split-K 8
    gemm_tc2<true><<<dim3(Q_RANKv / 128, BLv / 128, 8), 256, SMEM_GT2>>>(
        xh, xl, wqdh, wqdl, part, BLv, Q_RANKv, DIMv, DIMv, Q_RANKv,
        0, 0, (long long)BLv * Q_RANKv, 8, 256);
    reduce_k<<<dim3(BLv * Q_RANKv / 1024, 1), 256>>>(
        part, qlin, 8, (long long)BLv * Q_RANKv);

    // 2) kv_down (padded N=640), split-K 8
    gemm_tc2<true><<<dim3(KVPADv / 128, BLv / 128, 8), 256, SMEM_GT2>>>(
        xh, xl, wkvh, wkvl, part, BLv, KVPADv, DIMv, DIMv, KVPADv,
        0, 0, (long long)BLv * KVPADv, 8, 256);
    reduce_k<<<dim3(BLv * KVPADv / 1024, 1), 256>>>(
        part, kvpad, 8, (long long)BLv * KVPADv);

    // 3) rmsnorm -> qdn split
    rmsnorm_kernel<<<BLv, 256>>>(qlin, rms_q_w, qdnh, qdnl);

    // 4) q_up (256,3072,768), split-K 4
    gemm_tc2<true><<<dim3((Hv * QKv) / 128, BLv / 128, 4), 256, SMEM_GT2>>>(
        qdnh, qdnl, wquh, wqul, part, BLv, Hv * QKv, Q_RANKv, Q_RANKv, Hv * QKv,
        0, 0, (long long)BLv * Hv * QKv, 4, 192);
    reduce_k<<<dim3(BLv * Hv * QKv / 1024, 1), 256>>>(
        part, q, 4, (long long)BLv * Hv * QKv);

    // 5) rope (q + fresh k_rope)
    rope_kernel<<<BLv, 256>>>(q, kvpad, freq_cos, freq_sin);

    // 5b) split q
    convert_split<<<(BLv * Hv * QKv) / 2048, 256>>>(q, qsh, qsl);

    // 6) acat GEMM: per-head (M=256,N=512,K=128), BT=false -> scratch
    gemm_tc2<false><<<dim3(4, 2, Hv), 256, SMEM_GT2>>>(
        qsh, qsl, wvuh, wvul, part, 256, 512, Hv * QKv, 512, 512,
        192LL, (long long)256 * 512, (long long)256 * 512, 1, 128);
    assemble_acat<<<Bv * 512, 256>>>(part, qsh, qsl, acath, acatl);

    // 7) Kcat split
    build_kcat_kernel<<<dim3(MAXTv, Bv), 256>>>(kvc, krc, kvpad, kcath, kcatl);

    // 8) scores: batched (512,4096,K=576), BT=true
    gemm_tc2<true><<<dim3(MAXTv / 128, 4, Bv), 256, SMEM_GT2>>>(
        acath, acatl, kcath, kcatl, scores, 512, MAXTv, KCATv, KCATv, MAXTv,
        (long long)512 * KCATv, (long long)MAXTv * KCATv, (long long)512 * MAXTv,
        1, KCATv);

    // 9) softmax -> P split
    softmax_kernel<<<Bv * 512, 256>>>(scores, mask, ph, pl);

    // 10) PV: batched (512,512,K=4096), BT=false on Kcat[:, :512], split-K 4
    gemm_tc2<false><<<dim3(4, 4, Bv * 4), 256, SMEM_GT2>>>(
        ph, pl, kcath, kcatl, part, 512, KV_RANKv, MAXTv, KCATv, KV_RANKv,
        (long long)512 * MAXTv, (long long)MAXTv * KCATv, (long long)512 * KV_RANKv,
        4, 1024);
    reduce_pv<<<dim3(262144 / 1024, Bv), 256>>>(part, O2);

    // 11) split O2, o_up GEMM per head (M=256,N=128,K=512) -> o2f (reuse g_q)
    convert_split<<<(Bv * 512 * 512) / 2048, 256>>>(O2, o2sh, o2sl);
    gemm_tc2<true><<<dim3(1, 2, Hv), 256, SMEM_GT2>>>(
        o2sh, o2sl, wvuh + 128 * 512, wvul + 128 * 512, q,
        256, 128, 512, 512, Hv * D_Vv,
        (long long)256 * 512, (long long)256 * 512, 128LL, 1, 512);
    convert_split<<<(BLv * Hv * D_Vv) / 2048, 256>>>(q, o2h, o2l);

    // 12) out: (256,2048,K=2048), split-K 4
    gemm_tc2<true><<<dim3(DIMv / 128, BLv / 128, 4), 256, SMEM_GT2>>>(
        o2h, o2l, wouth, woutl, part, BLv, DIMv, DIMv, DIMv, DIMv,
        0, 0, (long long)BLv * DIMv, 4, 512);
    reduce_k<<<dim3(BLv * DIMv / 1024, 1), 256>>>(
        part, out, 4, (long long)BLv * DIMv);
}